// round 12
// baseline (speedup 1.0000x reference)
#include <cuda_runtime.h>
#include <math.h>
#include <stdint.h>

#define NLAYER 6
#define NH     16
#define DHEAD  96
#define DIMD   1024
#define INNER  1536
#define DFF    4096
#define NLAT   128
#define BT     32                 /* b*T sites                */
#define NMED   1024               /* media tokens per site    */
#define XROWS  (BT*NMED)          /* 32768 media rows total   */
#define RL     (BT*NLAT)          /* 4096 latent rows total   */
#define NKV    (NMED+NLAT)        /* 1152 KV per site         */
#define KV2    (2*INNER)          /* 3072 */

// ---------------- scratch (device globals; no allocation) ----------------
__device__ float    g_lat[(size_t)RL*DIMD];
__device__ float    g_q  [(size_t)RL*INNER];
__device__ float    g_kvl[(size_t)RL*KV2];
__device__ float    g_kvx[(size_t)XROWS*KV2];
__device__ float    g_s  [(size_t)BT*NH*NLAT*NKV];
__device__ int      g_cnt[8];
__device__ int      g_cidx[8*NMED];
__device__ float    g_kvbias[NLAYER*KV2];
// bf16 hi/lo activation planes
__device__ uint16_t g_lm_h[(size_t)RL*DIMD],    g_lm_l[(size_t)RL*DIMD];
__device__ uint16_t g_xm_h[(size_t)XROWS*DIMD], g_xm_l[(size_t)XROWS*DIMD];
__device__ uint16_t g_o_h [(size_t)RL*INNER],   g_o_l [(size_t)RL*INNER];
__device__ uint16_t g_hh  [(size_t)RL*DFF],     g_hl  [(size_t)RL*DFF];
// bf16 hi/lo transposed weight planes ([N][K] K-major)
__device__ uint16_t g_qwT_h [(size_t)NLAYER*INNER*DIMD], g_qwT_l [(size_t)NLAYER*INNER*DIMD];
__device__ uint16_t g_kvT_h [(size_t)NLAYER*KV2*DIMD],   g_kvT_l [(size_t)NLAYER*KV2*DIMD];
__device__ uint16_t g_kvTm_h[(size_t)NLAYER*KV2*DIMD],   g_kvTm_l[(size_t)NLAYER*KV2*DIMD];
__device__ uint16_t g_outT_h[(size_t)NLAYER*DIMD*INNER], g_outT_l[(size_t)NLAYER*DIMD*INNER];
__device__ uint16_t g_ff1T_h[(size_t)NLAYER*DFF*DIMD],   g_ff1T_l[(size_t)NLAYER*DFF*DIMD];
__device__ uint16_t g_ff2T_h[(size_t)NLAYER*DIMD*DFF],   g_ff2T_l[(size_t)NLAYER*DIMD*DFF];

// ======================= helpers =========================================
__device__ __forceinline__ uint32_t smem_u32(const void* p) {
    uint32_t r;
    asm("{ .reg .u64 t; cvta.to.shared.u64 t, %1; cvt.u32.u64 %0, t; }"
        : "=r"(r) : "l"(p));
    return r;
}
__device__ __forceinline__ uint16_t hi16(float v) {
    return (uint16_t)(__float_as_uint(v) >> 16);
}
__device__ __forceinline__ uint16_t lo16(float v) {
    float r = v - __uint_as_float(__float_as_uint(v) & 0xFFFF0000u);
    uint16_t o;
    asm("{.reg .b16 t; cvt.rn.bf16.f32 t, %1; mov.b16 %0, t;}" : "=h"(o) : "f"(r));
    return o;
}
__device__ __forceinline__ void ldsm4(uint32_t* r, uint32_t a) {
    asm volatile("ldmatrix.sync.aligned.m8n8.x4.shared.b16 {%0,%1,%2,%3}, [%4];"
        : "=r"(r[0]), "=r"(r[1]), "=r"(r[2]), "=r"(r[3]) : "r"(a));
}
__device__ __forceinline__ void ldsm2(uint32_t* r, uint32_t a) {
    asm volatile("ldmatrix.sync.aligned.m8n8.x2.shared.b16 {%0,%1}, [%2];"
        : "=r"(r[0]), "=r"(r[1]) : "r"(a));
}
__device__ __forceinline__ void mma16816(float* c, const uint32_t* a, const uint32_t* b) {
    asm volatile("mma.sync.aligned.m16n8k16.row.col.f32.bf16.bf16.f32 "
        "{%0,%1,%2,%3}, {%4,%5,%6,%7}, {%8,%9}, {%0,%1,%2,%3};"
        : "+f"(c[0]), "+f"(c[1]), "+f"(c[2]), "+f"(c[3])
        : "r"(a[0]), "r"(a[1]), "r"(a[2]), "r"(a[3]), "r"(b[0]), "r"(b[1]));
}

// ======================= bf16x3 tensor-core GEMM =========================
// C = epi(alpha * A @ Bt^T), operands pre-split bf16 hi/lo planes in gmem.
// EPI: 0 = alpha* ; 1 = C += ; 2 = split(gelu) -> Chi/Clo ; 3 = + bias[col]
#define ROWB   80
#define T_AHI  0
#define T_ALO  10240
#define T_BHI  20480
#define T_BLO  30720
#define STGSZ  40960
#define SMEM_TG (2*STGSZ)

template<int EPI, int CNT_SKIP>
__global__ void __launch_bounds__(256, 1)
tgemm(const uint16_t* __restrict__ Ahi, const uint16_t* __restrict__ Alo,
      const uint16_t* __restrict__ Bhi, const uint16_t* __restrict__ Blo,
      float* __restrict__ C, uint16_t* __restrict__ Chi, uint16_t* __restrict__ Clo,
      const float* __restrict__ bias, int M, int N, int K, float alpha) {
    if (CNT_SKIP) {
        int by = blockIdx.y;
        int b  = by >> 5;
        if ((by & 7) * 128 >= g_cnt[b]) return;
    }
    extern __shared__ char smem[];
    const uint32_t sb = smem_u32(smem);
    const int t = threadIdx.x;
    const int lane = t & 31, wid = t >> 5;
    const int wm = (wid >> 2) * 64;
    const int wn = (wid & 3) * 32;
    const int m0 = blockIdx.y * 128, n0 = blockIdx.x * 128;

    const uint16_t* Ah = Ahi + (size_t)m0 * K;
    const uint16_t* Al = Alo + (size_t)m0 * K;
    const uint16_t* Bh = Bhi + (size_t)n0 * K;
    const uint16_t* Bl = Blo + (size_t)n0 * K;

    float acc[4][4][4];
    #pragma unroll
    for (int i = 0; i < 4; i++)
        #pragma unroll
        for (int j = 0; j < 4; j++)
            #pragma unroll
            for (int r = 0; r < 4; r++) acc[i][j][r] = 0.f;

    const int nch = K / 32;

    auto stage = [&](int c, int buf) {
        char* st = smem + buf * STGSZ;
        #pragma unroll
        for (int p = 0; p < 4; p++) {
            const uint16_t* s = (p == 0) ? Ah : (p == 1) ? Al : (p == 2) ? Bh : Bl;
            #pragma unroll
            for (int h2 = 0; h2 < 2; h2++) {
                int idx = t + h2 * 256;
                int r = idx >> 2, q = idx & 3;
                uint4 v = *(const uint4*)(s + (size_t)r * K + c * 32 + q * 8);
                *(uint4*)(st + p * 10240 + r * ROWB + q * 16) = v;
            }
        }
    };

    const int arow  = wm + (lane & 7) + ((lane >> 3) & 1) * 8;
    const int akoff = ((lane >> 4) & 1) * 16;
    const int brow  = wn + (lane & 7);
    const int bkoff = ((lane >> 3) & 1) * 16;

    stage(0, 0);
    __syncthreads();

    for (int c = 0; c < nch; c++) {
        if (c + 1 < nch) stage(c + 1, (c + 1) & 1);
        const uint32_t base = sb + (c & 1) * STGSZ;
        #pragma unroll
        for (int ks = 0; ks < 2; ks++) {
            uint32_t ah[4][4], al[4][4], bh[4][2], bl[4][2];
            #pragma unroll
            for (int mt = 0; mt < 4; mt++) {
                uint32_t ad = base + (uint32_t)(arow + mt * 16) * ROWB + ks * 32 + akoff;
                ldsm4(ah[mt], ad + T_AHI);
                ldsm4(al[mt], ad + T_ALO);
            }
            #pragma unroll
            for (int nt = 0; nt < 4; nt++) {
                uint32_t bd = base + (uint32_t)(brow + nt * 8) * ROWB + ks * 32 + bkoff;
                ldsm2(bh[nt], bd + T_BHI);
                ldsm2(bl[nt], bd + T_BLO);
            }
            #pragma unroll
            for (int mt = 0; mt < 4; mt++)
                #pragma unroll
                for (int nt = 0; nt < 4; nt++) {
                    mma16816(acc[mt][nt], ah[mt], bh[nt]);
                    mma16816(acc[mt][nt], ah[mt], bl[nt]);
                    mma16816(acc[mt][nt], al[mt], bh[nt]);
                }
        }
        __syncthreads();
    }

    const int rl = lane >> 2;
    const int cl = (lane & 3) * 2;
    #pragma unroll
    for (int mt = 0; mt < 4; mt++) {
        #pragma unroll
        for (int nt = 0; nt < 4; nt++) {
            int gr = m0 + wm + mt * 16 + rl;
            int gc = n0 + wn + nt * 8 + cl;
            size_t off0 = (size_t)gr * N + gc;
            size_t off1 = (size_t)(gr + 8) * N + gc;
            float2 v0 = make_float2(acc[mt][nt][0] * alpha, acc[mt][nt][1] * alpha);
            float2 v1 = make_float2(acc[mt][nt][2] * alpha, acc[mt][nt][3] * alpha);
            if (EPI == 3) {
                float b0 = bias[gc], b1 = bias[gc + 1];
                v0.x += b0; v0.y += b1; v1.x += b0; v1.y += b1;
            }
            if (EPI == 1) {
                float2 c0 = *(float2*)(C + off0), c1 = *(float2*)(C + off1);
                v0.x += c0.x; v0.y += c0.y; v1.x += c1.x; v1.y += c1.y;
            }
            if (EPI == 2) {
                v0.x = 0.5f * v0.x * (1.0f + erff(v0.x * 0.70710678118654752f));
                v0.y = 0.5f * v0.y * (1.0f + erff(v0.y * 0.70710678118654752f));
                v1.x = 0.5f * v1.x * (1.0f + erff(v1.x * 0.70710678118654752f));
                v1.y = 0.5f * v1.y * (1.0f + erff(v1.y * 0.70710678118654752f));
                uint32_t h0 = __byte_perm(__float_as_uint(v0.x), __float_as_uint(v0.y), 0x7632);
                uint32_t h1 = __byte_perm(__float_as_uint(v1.x), __float_as_uint(v1.y), 0x7632);
                float l0x = v0.x - __uint_as_float(__float_as_uint(v0.x) & 0xFFFF0000u);
                float l0y = v0.y - __uint_as_float(__float_as_uint(v0.y) & 0xFFFF0000u);
                float l1x = v1.x - __uint_as_float(__float_as_uint(v1.x) & 0xFFFF0000u);
                float l1y = v1.y - __uint_as_float(__float_as_uint(v1.y) & 0xFFFF0000u);
                uint32_t l0, l1;
                asm("cvt.rn.bf16x2.f32 %0, %1, %2;" : "=r"(l0) : "f"(l0y), "f"(l0x));
                asm("cvt.rn.bf16x2.f32 %0, %1, %2;" : "=r"(l1) : "f"(l1y), "f"(l1x));
                *(uint32_t*)(Chi + off0) = h0;
                *(uint32_t*)(Chi + off1) = h1;
                *(uint32_t*)(Clo + off0) = l0;
                *(uint32_t*)(Clo + off1) = l1;
            } else {
                *(float2*)(C + off0) = v0;
                *(float2*)(C + off1) = v1;
            }
        }
    }
}

// ---------------- mask compaction ----------------------------------------
__global__ void compact_kernel(const float* __restrict__ vmask) {
    int b = blockIdx.x, t = threadIdx.x;
    __shared__ int woff[32];
    int valid = (vmask[b * NMED + t] > 0.f) ? 1 : 0;
    unsigned bal = __ballot_sync(0xffffffffu, valid);
    int lane = t & 31, wid = t >> 5;
    int pre = __popc(bal & ((1u << lane) - 1u));
    if (lane == 31) woff[wid] = __popc(bal);
    __syncthreads();
    if (t == 0) {
        int s = 0;
        #pragma unroll
        for (int w = 0; w < 32; w++) { int c = woff[w]; woff[w] = s; s += c; }
        g_cnt[b] = s;
    }
    __syncthreads();
    if (valid) g_cidx[b * NMED + woff[wid] + pre] = t;
}

// ---------------- weight transpose + split (+optional row gamma) ---------
__global__ void transpose_split_kernel(const float* __restrict__ src,
                                       uint16_t* __restrict__ dhi,
                                       uint16_t* __restrict__ dlo,
                                       int R, int Ccols,
                                       const float* __restrict__ gamma) {
    __shared__ float tile[32][33];
    size_t zoff = (size_t)blockIdx.z * R * Ccols;
    int r0 = blockIdx.y * 32, c0 = blockIdx.x * 32;
    int tx = threadIdx.x, ty = threadIdx.y;
    #pragma unroll
    for (int i = ty; i < 32; i += 8) {
        float v = src[zoff + (size_t)(r0 + i) * Ccols + c0 + tx];
        if (gamma) v *= gamma[blockIdx.z * R + r0 + i];
        tile[i][tx] = v;
    }
    __syncthreads();
    int tid = ty * 32 + tx;
    int i = tid >> 3, jp = tid & 7;
    float v0 = tile[jp*4+0][i], v1 = tile[jp*4+1][i];
    float v2 = tile[jp*4+2][i], v3 = tile[jp*4+3][i];
    uint32_t h01 = __byte_perm(__float_as_uint(v0), __float_as_uint(v1), 0x7632);
    uint32_t h23 = __byte_perm(__float_as_uint(v2), __float_as_uint(v3), 0x7632);
    float l0 = v0 - __uint_as_float(__float_as_uint(v0) & 0xFFFF0000u);
    float l1 = v1 - __uint_as_float(__float_as_uint(v1) & 0xFFFF0000u);
    float l2 = v2 - __uint_as_float(__float_as_uint(v2) & 0xFFFF0000u);
    float l3 = v3 - __uint_as_float(__float_as_uint(v3) & 0xFFFF0000u);
    uint32_t l01, l23;
    asm("cvt.rn.bf16x2.f32 %0, %1, %2;" : "=r"(l01) : "f"(l1), "f"(l0));
    asm("cvt.rn.bf16x2.f32 %0, %1, %2;" : "=r"(l23) : "f"(l3), "f"(l2));
    size_t doff = zoff + (size_t)(c0 + i) * R + r0 + jp * 4;
    *(uint2*)(dhi + doff) = make_uint2(h01, h23);
    *(uint2*)(dlo + doff) = make_uint2(l01, l23);
}

// ---------------- kv bias row: bias[l][n] = sum_k b[l][k] * w[l][k][n] ---
__global__ void kvbias_kernel(const float* __restrict__ lb,
                              const float* __restrict__ w) {
    int l = blockIdx.y;
    int n = blockIdx.x * 256 + threadIdx.x;
    const float* bb = lb + l * DIMD;
    const float* ww = w + (size_t)l * DIMD * KV2;
    float s = 0.f;
    #pragma unroll 8
    for (int k = 0; k < DIMD; k++) s += bb[k] * ww[(size_t)k * KV2 + n];
    g_kvbias[l * KV2 + n] = s;
}

// ---------------- broadcast latents --------------------------------------
__global__ void bcast_kernel(const float* __restrict__ lat) {
    int i = blockIdx.x * 256 + threadIdx.x;
    int row = i >> 10;
    int col = i & 1023;
    g_lat[i] = lat[((row & (NLAT-1)) << 10) + col];
}

// ---------------- LayerNorm core -----------------------------------------
__device__ __forceinline__ void ln_stats(const float* __restrict__ x, int t,
                                         float* red, float* v, float& mu, float& inv) {
    float s = 0.f;
    #pragma unroll
    for (int i = 0; i < 4; i++) { v[i] = x[t + 256*i]; s += v[i]; }
    red[t] = s; __syncthreads();
    #pragma unroll
    for (int o = 128; o > 0; o >>= 1) { if (t < o) red[t] += red[t+o]; __syncthreads(); }
    mu = red[0] * (1.f/DIMD);
    __syncthreads();
    float s2 = 0.f;
    #pragma unroll
    for (int i = 0; i < 4; i++) { float d = v[i]-mu; s2 += d*d; }
    red[t] = s2; __syncthreads();
    #pragma unroll
    for (int o = 128; o > 0; o >>= 1) { if (t < o) red[t] += red[t+o]; __syncthreads(); }
    inv = rsqrtf(red[0]*(1.f/DIMD) + 1e-5f);
}

// fp32 output (final LN)
__global__ void ln_kernel(const float* __restrict__ in,
                          const float* __restrict__ gg,
                          const float* __restrict__ bb,
                          float* __restrict__ out) {
    __shared__ float red[256];
    int row = blockIdx.x, t = threadIdx.x;
    float v[4], mu, inv;
    ln_stats(in + (size_t)row * DIMD, t, red, v, mu, inv);
    float* y = out + (size_t)row * DIMD;
    #pragma unroll
    for (int i = 0; i < 4; i++) { int c = t + 256*i; y[c] = (v[i]-mu)*inv*gg[c] + bb[c]; }
}

// split bf16 output (latent LNs)
__global__ void ln_split_kernel(const float* __restrict__ in,
                                const float* __restrict__ gg,
                                const float* __restrict__ bb,
                                uint16_t* __restrict__ ohi,
                                uint16_t* __restrict__ olo) {
    __shared__ float red[256];
    int row = blockIdx.x, t = threadIdx.x;
    float v[4], mu, inv;
    ln_stats(in + (size_t)row * DIMD, t, red, v, mu, inv);
    size_t base = (size_t)row * DIMD;
    #pragma unroll
    for (int i = 0; i < 4; i++) {
        int c = t + 256*i;
        float y = (v[i]-mu)*inv*gg[c] + bb[c];
        ohi[base + c] = hi16(y);
        olo[base + c] = lo16(y);
    }
}

// media LN (pure hat, gamma folded into weights), compaction gather, once
__global__ void ln_media_split_kernel(const float* __restrict__ x) {
    int r = blockIdx.x;
    int bt = r >> 10, i = r & (NMED-1);
    int b = bt >> 2;
    if (i >= g_cnt[b]) return;
    int src = (bt << 10) + g_cidx[b * NMED + i];
    __shared__ float red[256];
    int t = threadIdx.x;
    float v[4], mu, inv;
    ln_stats(x + (size_t)src * DIMD, t, red, v, mu, inv);
    size_t base = (size_t)r * DIMD;
    #pragma unroll
    for (int j = 0; j < 4; j++) {
        int c = t + 256*j;
        float y = (v[j]-mu)*inv;
        g_xm_h[base + c] = hi16(y);
        g_xm_l[base + c] = lo16(y);
    }
}

// ---- scores: block = (bt, h, jt) ----------------------------------------
__global__ void __launch_bounds__(256)
scores_kernel() {
    int bt = blockIdx.x, h = blockIdx.y, jt = blockIdx.z;
    int b  = bt >> 2;
    int j0 = jt * 128;
    int t = threadIdx.x;
    int cnt = g_cnt[b];
    size_t base = ((size_t)(bt*NH + h)) * NLAT;

    if (j0 < NMED && j0 >= cnt) {
        for (int idx = t; idx < 128*128; idx += 256) {
            int i = idx >> 7, j = idx & 127;
            g_s[(base + i)*NKV + j0 + j] = -INFINITY;
        }
        return;
    }

    __shared__ float Qs[32][129];
    __shared__ float Ks[32][129];
    int tx = t & 15, ty = t >> 4;

    float acc[8][8];
    #pragma unroll
    for (int i = 0; i < 8; i++)
        #pragma unroll
        for (int j = 0; j < 8; j++) acc[i][j] = 0.f;

    for (int dc = 0; dc < DHEAD; dc += 32) {
        for (int idx = t; idx < 128*32; idx += 256) {
            int i = idx >> 5, d = idx & 31;
            Qs[d][i] = g_q[((size_t)(bt*NLAT + i))*INNER + h*DHEAD + dc + d];
        }
        for (int idx = t; idx < 128*32; idx += 256) {
            int jj = idx >> 5, d = idx & 31;
            int j = j0 + jj;
            float kv = (j < NMED)
                ? g_kvx[((size_t)(bt*NMED + j))*KV2 + h*DHEAD + dc + d]
                : g_kvl[((size_t)(bt*NLAT + (j - NMED)))*KV2 + h*DHEAD + dc + d];
            Ks[d][jj] = kv;
        }
        __syncthreads();
        #pragma unroll 8
        for (int d = 0; d < 32; d++) {
            float ra[8], rb[8];
            #pragma unroll
            for (int i = 0; i < 8; i++) ra[i] = Qs[d][ty*8 + i];
            #pragma unroll
            for (int j = 0; j < 4; j++) { rb[j] = Ks[d][tx*4 + j]; rb[j+4] = Ks[d][64 + tx*4 + j]; }
            #pragma unroll
            for (int i = 0; i < 8; i++)
                #pragma unroll
                for (int j = 0; j < 8; j++) acc[i][j] += ra[i]*rb[j];
        }
        __syncthreads();
    }

    #pragma unroll
    for (int i = 0; i < 8; i++) {
        int row = ty*8 + i;
        #pragma unroll
        for (int j = 0; j < 8; j++) {
            int cc = (j < 4) ? (tx*4 + j) : (64 + tx*4 + j - 4);
            int jg = j0 + cc;
            float v = acc[i][j];
            if (jg < NMED && jg >= cnt) v = -INFINITY;
            g_s[(base + row)*NKV + jg] = v;
        }
    }
}

// ---------------- softmax over 1152 KV -----------------------------------
__global__ void softmax_kernel() {
    size_t row = blockIdx.x;
    float* s = g_s + row * (size_t)NKV;
    int t = threadIdx.x;
    __shared__ float red[256];
    float m = -INFINITY;
    for (int j = t; j < NKV; j += 256) m = fmaxf(m, s[j]);
    red[t] = m; __syncthreads();
    #pragma unroll
    for (int o = 128; o > 0; o >>= 1) { if (t < o) red[t] = fmaxf(red[t], red[t+o]); __syncthreads(); }
    m = red[0]; __syncthreads();
    float e[5]; int c = 0; float sum = 0.f;
    for (int j = t; j < NKV; j += 256) { e[c] = expf(s[j] - m); sum += e[c]; c++; }
    red[t] = sum; __syncthreads();
    #pragma unroll
    for (int o = 128; o > 0; o >>= 1) { if (t < o) red[t] += red[t+o]; __syncthreads(); }
    float inv = 1.f / red[0];
    c = 0;
    for (int j = t; j < NKV; j += 256) { s[j] = e[c] * inv; c++; }
}

// ---------------- O = P V (writes split bf16) ----------------------------
__global__ void __launch_bounds__(256)
av_kernel() {
    int bt = blockIdx.x, h = blockIdx.y;
    int b = bt >> 2;
    int cnt = g_cnt[b];
    __shared__ float Ps[32][133];
    __shared__ float Vs[32][96];
    int t = threadIdx.x, tx = t & 15, ty = t >> 4;

    float acc[8][6];
    #pragma unroll
    for (int i = 0; i < 8; i++)
        #pragma unroll
        for (int d = 0; d < 6; d++) acc[i][d] = 0.f;

    size_t prow0 = (size_t)(bt*NH + h) * NLAT;
    for (int jc = 0; jc < NKV; jc += 32) {
        if (jc < NMED && jc >= cnt) continue;
        for (int idx = t; idx < 128*32; idx += 256) {
            int i = idx >> 5, jj = idx & 31;
            Ps[jj][i] = g_s[(prow0 + i)*NKV + jc + jj];
        }
        for (int idx = t; idx < 32*96; idx += 256) {
            int jj = idx / 96, d = idx % 96;
            int j = jc + jj;
            float vv;
            if (j < NMED) {
                vv = (j < cnt) ? g_kvx[((size_t)(bt*NMED + j))*KV2 + INNER + h*DHEAD + d] : 0.f;
            } else {
                vv = g_kvl[((size_t)(bt*NLAT + (j - NMED)))*KV2 + INNER + h*DHEAD + d];
            }
            Vs[jj][d] = vv;
        }
        __syncthreads();
        #pragma unroll 8
        for (int jj = 0; jj < 32; jj++) {
            float ra[8], rb[6];
            #pragma unroll
            for (int i = 0; i < 8; i++) ra[i] = Ps[jj][ty*8 + i];
            #pragma unroll
            for (int d = 0; d < 6; d++) rb[d] = Vs[jj][tx + 16*d];
            #pragma unroll
            for (int i = 0; i < 8; i++)
                #pragma unroll
                for (int d = 0; d < 6; d++) acc[i][d] += ra[i]*rb[d];
        }
        __syncthreads();
    }

    #pragma unroll
    for (int i = 0; i < 8; i++)
        #pragma unroll
        for (int d = 0; d < 6; d++) {
            size_t idx = ((size_t)(bt*NLAT + ty*8 + i))*INNER + h*DHEAD + tx + 16*d;
            float v = acc[i][d];
            g_o_h[idx] = hi16(v);
            g_o_l[idx] = lo16(v);
        }
}

// ---------------- host orchestration (graph-capturable) ------------------
extern "C" void kernel_launch(void* const* d_in, const int* in_sizes, int n_in,
                              void* d_out, int out_size) {
    (void)in_sizes; (void)n_in; (void)out_size;
    const float* x       = (const float*)d_in[0];
    const float* vmask   = (const float*)d_in[1];
    const float* latents = (const float*)d_in[2];
    const float* ln_m_g  = (const float*)d_in[3];
    const float* ln_m_b  = (const float*)d_in[4];
    const float* ln_l_g  = (const float*)d_in[5];
    const float* ln_l_b  = (const float*)d_in[6];
    const float* q_w     = (const float*)d_in[7];
    const float* kv_w    = (const float*)d_in[8];
    const float* out_w   = (const float*)d_in[9];
    const float* ff_ln_g = (const float*)d_in[10];
    const float* ff_ln_b = (const float*)d_in[11];
    const float* ff_w1   = (const float*)d_in[12];
    const float* ff_w2   = (const float*)d_in[13];
    const float* fn_g    = (const float*)d_in[14];
    const float* fn_b    = (const float*)d_in[15];
    float* out = (float*)d_out;

    float *p_lat, *p_q, *p_kvl, *p_kvx, *p_bias;
    uint16_t *p_lm_h, *p_lm_l, *p_o_h, *p_o_l, *p_hh, *p_hl;
    uint16_t *p_qwT_h, *p_qwT_l, *p_kvT_h, *p_kvT_l, *p_kvTm_h, *p_kvTm_l;
    uint16_t *p_outT_h, *p_outT_l, *p_ff1T_h, *p_ff1T_l, *p_ff2T_h, *p_ff2T_l;
    uint16_t *p_xm_h, *p_xm_l;
    cudaGetSymbolAddress((void**)&p_lat, g_lat);
    cudaGetSymbolAddress((void**)&p_q,   g_q);
    cudaGetSymbolAddress((void**)&p_kvl, g_kvl);
    cudaGetSymbolAddress((void**)&p_kvx, g_kvx);
    cudaGetSymbolAddress((void**)&p_bias, g_kvbias);
    cudaGetSymbolAddress((void**)&p_lm_h, g_lm_h);
    cudaGetSymbolAddress((void**)&p_lm_l, g_lm_l);
    cudaGetSymbolAddress((void**)&p_xm_h, g_xm_h);
    cudaGetSymbolAddress((void**)&p_xm_l, g_xm_l);
    cudaGetSymbolAddress((void**)&p_o_h,  g_o_h);
    cudaGetSymbolAddress((void**)&p_o_l,  g_o_l);
    cudaGetSymbolAddress((void**)&p_hh,   g_hh);
    cudaGetSymbolAddress((void**)&p_hl,   g_hl);
    cudaGetSymbolAddress((void**)&p_qwT_h,  g_qwT_h);
    cudaGetSymbolAddress((void**)&p_qwT_l,  g_qwT_l);
    cudaGetSymbolAddress((void**)&p_kvT_h,  g_kvT_h);
    cudaGetSymbolAddress((void**)&p_kvT_l,  g_kvT_l);
    cudaGetSymbolAddress((void**)&p_kvTm_h, g_kvTm_h);
    cudaGetSymbolAddress((void**)&p_kvTm_l, g_kvTm_l);
    cudaGetSymbolAddress((void**)&p_outT_h, g_outT_h);
    cudaGetSymbolAddress((void**)&p_outT_l, g_outT_l);
    cudaGetSymbolAddress((void**)&p_ff1T_h, g_ff1T_h);
    cudaGetSymbolAddress((void**)&p_ff1T_l, g_ff1T_l);
    cudaGetSymbolAddress((void**)&p_ff2T_h, g_ff2T_h);
    cudaGetSymbolAddress((void**)&p_ff2T_l, g_ff2T_l);

    cudaFuncSetAttribute((const void*)tgemm<0,0>, cudaFuncAttributeMaxDynamicSharedMemorySize, SMEM_TG);
    cudaFuncSetAttribute((const void*)tgemm<3,1>, cudaFuncAttributeMaxDynamicSharedMemorySize, SMEM_TG);
    cudaFuncSetAttribute((const void*)tgemm<1,0>, cudaFuncAttributeMaxDynamicSharedMemorySize, SMEM_TG);
    cudaFuncSetAttribute((const void*)tgemm<2,0>, cudaFuncAttributeMaxDynamicSharedMemorySize, SMEM_TG);

    const float scale = 1.0f / sqrtf((float)DHEAD);
    dim3 tb(32, 8);

    // one-time weight prep: transpose + bf16 split (media kv folds gamma)
    transpose_split_kernel<<<dim3(INNER/32, DIMD/32, NLAYER), tb>>>(q_w,   p_qwT_h,  p_qwT_l,  DIMD,  INNER, nullptr);
    transpose_split_kernel<<<dim3(KV2/32,   DIMD/32, NLAYER), tb>>>(kv_w,  p_kvT_h,  p_kvT_l,  DIMD,  KV2,   nullptr);
    transpose_split_kernel<<<dim3(KV2/32,   DIMD/32, NLAYER), tb>>>(kv_w,  p_kvTm_h, p_kvTm_l, DIMD,  KV2,   ln_m_g);
    transpose_split_kernel<<<dim3(DIMD/32, INNER/32, NLAYER), tb>>>(out_w, p_outT_h, p_outT_l, INNER, DIMD,  nullptr);
    transpose_split_kernel<<<dim3(DFF/32,   DIMD/32, NLAYER), tb>>>(ff_w1, p_ff1T_h, p_ff1T_l, DIMD,  DFF,   nullptr);
    transpose_split_kernel<<<dim3(DIMD/32,  DFF/32,  NLAYER), tb>>>(ff_w2, p_ff2T_h, p_ff2T_l, DFF,   DIMD,  nullptr);
    kvbias_kernel<<<dim3(KV2/256, NLAYER), 256>>>(ln_m_b, kv_w);

    compact_kernel<<<8, 1024>>>(vmask);
    bcast_kernel<<<RL*DIMD/256, 256>>>(latents);
    ln_media_split_kernel<<<XROWS, 256>>>(x);   // once: gamma/beta folded

    for (int l = 0; l < NLAYER; l++) {
        ln_split_kernel<<<RL, 256>>>(p_lat, ln_l_g + l*DIMD, ln_l_b + l*DIMD, p_lm_h, p_lm_l);

        tgemm<0,0><<<dim3(INNER/128, RL/128), 256, SMEM_TG>>>(
            p_lm_h, p_lm_l, p_qwT_h + (size_t)l*INNER*DIMD, p_qwT_l + (size_t)l*INNER*DIMD,
            p_q, nullptr, nullptr, nullptr, RL, INNER, DIMD, scale);
        tgemm<0,0><<<dim3(KV2/128, RL/128), 256, SMEM_TG>>>(
            p_lm_h, p_lm_l, p_kvT_h + (size_t)l*KV2*DIMD, p_kvT_l + (size_t)l*KV2*DIMD,
            p_kvl, nullptr, nullptr, nullptr, RL, KV2, DIMD, 1.f);
        tgemm<3,1><<<dim3(KV2/128, XROWS/128), 256, SMEM_TG>>>(
            p_xm_h, p_xm_l, p_kvTm_h + (size_t)l*KV2*DIMD, p_kvTm_l + (size_t)l*KV2*DIMD,
            p_kvx, nullptr, nullptr, p_bias + l*KV2, XROWS, KV2, DIMD, 1.f);

        scores_kernel<<<dim3(BT, NH, NKV/128), 256>>>();
        softmax_kernel<<<BT*NH*NLAT, 256>>>();
        av_kernel<<<dim3(BT, NH), 256>>>();

        tgemm<1,0><<<dim3(DIMD/128, RL/128), 256, SMEM_TG>>>(
            p_o_h, p_o_l, p_outT_h + (size_t)l*DIMD*INNER, p_outT_l + (size_t)l*DIMD*INNER,
            p_lat, nullptr, nullptr, nullptr, RL, DIMD, INNER, 1.f);

        ln_split_kernel<<<RL, 256>>>(p_lat, ff_ln_g + l*DIMD, ff_ln_b + l*DIMD, p_lm_h, p_lm_l);
        tgemm<2,0><<<dim3(DFF/128, RL/128), 256, SMEM_TG>>>(
            p_lm_h, p_lm_l, p_ff1T_h + (size_t)l*DFF*DIMD, p_ff1T_l + (size_t)l*DFF*DIMD,
            nullptr, p_hh, p_hl, nullptr, RL, DFF, DIMD, 1.f);
        tgemm<1,0><<<dim3(DIMD/128, RL/128), 256, SMEM_TG>>>(
            p_hh, p_hl, p_ff2T_h + (size_t)l*DIMD*DFF, p_ff2T_l + (size_t)l*DIMD*DFF,
            p_lat, nullptr, nullptr, nullptr, RL, DIMD, DFF, 1.f);
    }

    ln_kernel<<<RL, 256>>>(p_lat, fn_g, fn_b, out);
}

// round 13
// speedup vs baseline: 1.0775x; 1.0775x over previous
#include <cuda_runtime.h>
#include <math.h>
#include <stdint.h>

#define NLAYER 6
#define NH     16
#define DHEAD  96
#define DIMD   1024
#define INNER  1536
#define DFF    4096
#define NLAT   128
#define BT     32                 /* b*T sites                */
#define NMED   1024               /* media tokens per site    */
#define XROWS  (BT*NMED)          /* 32768 media rows total   */
#define RL     (BT*NLAT)          /* 4096 latent rows total   */
#define NKV    (NMED+NLAT)        /* 1152 KV per site         */
#define KV2    (2*INNER)          /* 3072 */

// ---------------- scratch (device globals; no allocation) ----------------
// packed split layout: per (row, kchunk) 128B = [32 x bf16 hi || 32 x bf16 lo]
// index(row,k) hi = (row*(K/32) + (k>>5))*64 + (k&31) ; lo = +32
__device__ float    g_lat[(size_t)RL*DIMD];
__device__ float    g_q  [(size_t)RL*INNER];
__device__ float    g_kvl[(size_t)RL*KV2];
__device__ float    g_kvx[(size_t)XROWS*KV2];
__device__ float    g_s  [(size_t)BT*NH*NLAT*NKV];
__device__ int      g_cnt[8];
__device__ int      g_cidx[8*NMED];
__device__ float    g_kvbias[NLAYER*KV2];
// packed activations
__device__ uint16_t g_lm_p[(size_t)RL*2*DIMD];
__device__ uint16_t g_xm_p[(size_t)XROWS*2*DIMD];
__device__ uint16_t g_o_p [(size_t)RL*2*INNER];
__device__ uint16_t g_h_p [(size_t)RL*2*DFF];
// packed transposed weights ([N][2K] K-major chunks)
__device__ uint16_t g_qwT_p [(size_t)NLAYER*INNER*2*DIMD];
__device__ uint16_t g_kvT_p [(size_t)NLAYER*KV2*2*DIMD];
__device__ uint16_t g_kvTm_p[(size_t)NLAYER*KV2*2*DIMD];
__device__ uint16_t g_outT_p[(size_t)NLAYER*DIMD*2*INNER];
__device__ uint16_t g_ff1T_p[(size_t)NLAYER*DFF*2*DIMD];
__device__ uint16_t g_ff2T_p[(size_t)NLAYER*DIMD*2*DFF];

// ======================= helpers =========================================
__device__ __forceinline__ uint32_t smem_u32(const void* p) {
    uint32_t r;
    asm("{ .reg .u64 t; cvta.to.shared.u64 t, %1; cvt.u32.u64 %0, t; }"
        : "=r"(r) : "l"(p));
    return r;
}
__device__ __forceinline__ uint16_t hi16(float v) {
    return (uint16_t)(__float_as_uint(v) >> 16);
}
__device__ __forceinline__ uint16_t lo16(float v) {
    float r = v - __uint_as_float(__float_as_uint(v) & 0xFFFF0000u);
    uint16_t o;
    asm("{.reg .b16 t; cvt.rn.bf16.f32 t, %1; mov.b16 %0, t;}" : "=h"(o) : "f"(r));
    return o;
}
__device__ __forceinline__ void ldsm4(uint32_t* r, uint32_t a) {
    asm volatile("ldmatrix.sync.aligned.m8n8.x4.shared.b16 {%0,%1,%2,%3}, [%4];"
        : "=r"(r[0]), "=r"(r[1]), "=r"(r[2]), "=r"(r[3]) : "r"(a));
}
__device__ __forceinline__ void ldsm2(uint32_t* r, uint32_t a) {
    asm volatile("ldmatrix.sync.aligned.m8n8.x2.shared.b16 {%0,%1}, [%2];"
        : "=r"(r[0]), "=r"(r[1]) : "r"(a));
}
__device__ __forceinline__ void mma16816(float* c, const uint32_t* a, const uint32_t* b) {
    asm volatile("mma.sync.aligned.m16n8k16.row.col.f32.bf16.bf16.f32 "
        "{%0,%1,%2,%3}, {%4,%5,%6,%7}, {%8,%9}, {%0,%1,%2,%3};"
        : "+f"(c[0]), "+f"(c[1]), "+f"(c[2]), "+f"(c[3])
        : "r"(a[0]), "r"(a[1]), "r"(a[2]), "r"(a[3]), "r"(b[0]), "r"(b[1]));
}

// ======================= bf16x3 tensor-core GEMM =========================
// C = epi(alpha * A @ Bt^T); A,B packed hi/lo chunk-interleaved in gmem.
// EPI: 0 = alpha* ; 1 = C += ; 2 = gelu -> packed Cp ; 3 = + bias[col]
#define ROWB   80
#define P_AHI  0
#define P_ALO  10304              /* +64B skew: hi/lo STS phases bank-disjoint */
#define P_BHI  20608
#define P_BLO  30912
#define STGSZ  41216
#define SMEM_TG (2*STGSZ)

template<int EPI, int CNT_SKIP>
__global__ void __launch_bounds__(256, 1)
tgemm(const uint16_t* __restrict__ Ap, const uint16_t* __restrict__ Bp,
      float* __restrict__ C, uint16_t* __restrict__ Cp,
      const float* __restrict__ bias, int M, int N, int K, float alpha) {
    if (CNT_SKIP) {
        int by = blockIdx.y;
        int b  = by >> 5;
        if ((by & 7) * 128 >= g_cnt[b]) return;
    }
    extern __shared__ char smem[];
    const uint32_t sb = smem_u32(smem);
    const int t = threadIdx.x;
    const int lane = t & 31, wid = t >> 5;
    const int wm = (wid >> 2) * 64;
    const int wn = (wid & 3) * 32;
    const int m0 = blockIdx.y * 128, n0 = blockIdx.x * 128;
    const int K2 = 2 * K;

    const uint16_t* Ar = Ap + (size_t)m0 * K2;
    const uint16_t* Br = Bp + (size_t)n0 * K2;

    float acc[4][4][4];
    #pragma unroll
    for (int i = 0; i < 4; i++)
        #pragma unroll
        for (int j = 0; j < 4; j++)
            #pragma unroll
            for (int r = 0; r < 4; r++) acc[i][j][r] = 0.f;

    const int nch = K / 32;
    const int qsel = t & 7;                      // thread-constant
    const uint32_t aplane = (qsel & 4) ? P_ALO : P_AHI;
    const uint32_t bplane = (qsel & 4) ? P_BLO : P_BHI;
    const uint32_t qoff   = (qsel & 3) * 16;

    auto stage = [&](int c, int buf) {
        char* st = smem + buf * STGSZ;
        #pragma unroll
        for (int h2 = 0; h2 < 4; h2++) {
            int r = (t >> 3) + 32 * h2;
            uint4 v = *(const uint4*)(Ar + (size_t)r * K2 + c * 64 + qsel * 8);
            *(uint4*)(st + aplane + r * ROWB + qoff) = v;
        }
        #pragma unroll
        for (int h2 = 0; h2 < 4; h2++) {
            int r = (t >> 3) + 32 * h2;
            uint4 v = *(const uint4*)(Br + (size_t)r * K2 + c * 64 + qsel * 8);
            *(uint4*)(st + bplane + r * ROWB + qoff) = v;
        }
    };

    const int arow  = wm + (lane & 7) + ((lane >> 3) & 1) * 8;
    const int akoff = ((lane >> 4) & 1) * 16;
    const int brow  = wn + (lane & 7);
    const int bkoff = ((lane >> 3) & 1) * 16;

    stage(0, 0);
    __syncthreads();

    for (int c = 0; c < nch; c++) {
        if (c + 1 < nch) stage(c + 1, (c + 1) & 1);
        const uint32_t base = sb + (c & 1) * STGSZ;
        #pragma unroll
        for (int ks = 0; ks < 2; ks++) {
            uint32_t ah[4][4], al[4][4], bh[4][2], bl[4][2];
            #pragma unroll
            for (int mt = 0; mt < 4; mt++) {
                uint32_t ad = base + (uint32_t)(arow + mt * 16) * ROWB + ks * 32 + akoff;
                ldsm4(ah[mt], ad + P_AHI);
                ldsm4(al[mt], ad + P_ALO);
            }
            #pragma unroll
            for (int nt = 0; nt < 4; nt++) {
                uint32_t bd = base + (uint32_t)(brow + nt * 8) * ROWB + ks * 32 + bkoff;
                ldsm2(bh[nt], bd + P_BHI);
                ldsm2(bl[nt], bd + P_BLO);
            }
            #pragma unroll
            for (int mt = 0; mt < 4; mt++)
                #pragma unroll
                for (int nt = 0; nt < 4; nt++) {
                    mma16816(acc[mt][nt], ah[mt], bh[nt]);
                    mma16816(acc[mt][nt], ah[mt], bl[nt]);
                    mma16816(acc[mt][nt], al[mt], bh[nt]);
                }
        }
        __syncthreads();
    }

    const int rl = lane >> 2;
    const int cl = (lane & 3) * 2;
    #pragma unroll
    for (int mt = 0; mt < 4; mt++) {
        #pragma unroll
        for (int nt = 0; nt < 4; nt++) {
            int gr = m0 + wm + mt * 16 + rl;
            int gc = n0 + wn + nt * 8 + cl;
            float2 v0 = make_float2(acc[mt][nt][0] * alpha, acc[mt][nt][1] * alpha);
            float2 v1 = make_float2(acc[mt][nt][2] * alpha, acc[mt][nt][3] * alpha);
            if (EPI == 3) {
                float b0 = bias[gc], b1 = bias[gc + 1];
                v0.x += b0; v0.y += b1; v1.x += b0; v1.y += b1;
            }
            if (EPI == 1) {
                size_t off0 = (size_t)gr * N + gc;
                size_t off1 = (size_t)(gr + 8) * N + gc;
                float2 c0 = *(float2*)(C + off0), c1 = *(float2*)(C + off1);
                v0.x += c0.x; v0.y += c0.y; v1.x += c1.x; v1.y += c1.y;
                *(float2*)(C + off0) = v0;
                *(float2*)(C + off1) = v1;
            } else if (EPI == 2) {
                v0.x = 0.5f * v0.x * (1.0f + erff(v0.x * 0.70710678118654752f));
                v0.y = 0.5f * v0.y * (1.0f + erff(v0.y * 0.70710678118654752f));
                v1.x = 0.5f * v1.x * (1.0f + erff(v1.x * 0.70710678118654752f));
                v1.y = 0.5f * v1.y * (1.0f + erff(v1.y * 0.70710678118654752f));
                uint32_t h0 = __byte_perm(__float_as_uint(v0.x), __float_as_uint(v0.y), 0x7632);
                uint32_t h1 = __byte_perm(__float_as_uint(v1.x), __float_as_uint(v1.y), 0x7632);
                float l0x = v0.x - __uint_as_float(__float_as_uint(v0.x) & 0xFFFF0000u);
                float l0y = v0.y - __uint_as_float(__float_as_uint(v0.y) & 0xFFFF0000u);
                float l1x = v1.x - __uint_as_float(__float_as_uint(v1.x) & 0xFFFF0000u);
                float l1y = v1.y - __uint_as_float(__float_as_uint(v1.y) & 0xFFFF0000u);
                uint32_t l0, l1;
                asm("cvt.rn.bf16x2.f32 %0, %1, %2;" : "=r"(l0) : "f"(l0y), "f"(l0x));
                asm("cvt.rn.bf16x2.f32 %0, %1, %2;" : "=r"(l1) : "f"(l1y), "f"(l1x));
                int chunk = gc >> 5, pos = gc & 31;
                size_t p0 = ((size_t)gr * (N >> 5) + chunk) * 64 + pos;
                size_t p1 = ((size_t)(gr + 8) * (N >> 5) + chunk) * 64 + pos;
                *(uint32_t*)(Cp + p0)      = h0;
                *(uint32_t*)(Cp + p0 + 32) = l0;
                *(uint32_t*)(Cp + p1)      = h1;
                *(uint32_t*)(Cp + p1 + 32) = l1;
            } else {
                size_t off0 = (size_t)gr * N + gc;
                size_t off1 = (size_t)(gr + 8) * N + gc;
                *(float2*)(C + off0) = v0;
                *(float2*)(C + off1) = v1;
            }
        }
    }
}

// ---------------- mask compaction ----------------------------------------
__global__ void compact_kernel(const float* __restrict__ vmask) {
    int b = blockIdx.x, t = threadIdx.x;
    __shared__ int woff[32];
    int valid = (vmask[b * NMED + t] > 0.f) ? 1 : 0;
    unsigned bal = __ballot_sync(0xffffffffu, valid);
    int lane = t & 31, wid = t >> 5;
    int pre = __popc(bal & ((1u << lane) - 1u));
    if (lane == 31) woff[wid] = __popc(bal);
    __syncthreads();
    if (t == 0) {
        int s = 0;
        #pragma unroll
        for (int w = 0; w < 32; w++) { int c = woff[w]; woff[w] = s; s += c; }
        g_cnt[b] = s;
    }
    __syncthreads();
    if (valid) g_cidx[b * NMED + woff[wid] + pre] = t;
}

// ------- weight transpose + split into packed layout (+opt row gamma) ----
__global__ void transpose_split_kernel(const float* __restrict__ src,
                                       uint16_t* __restrict__ dp,
                                       int R, int Ccols,
                                       const float* __restrict__ gamma) {
    __shared__ float tile[32][33];
    size_t zoff = (size_t)blockIdx.z * R * Ccols;
    size_t dz   = (size_t)blockIdx.z * Ccols * 2 * R;
    int r0 = blockIdx.y * 32, c0 = blockIdx.x * 32;
    int tx = threadIdx.x, ty = threadIdx.y;
    #pragma unroll
    for (int i = ty; i < 32; i += 8) {
        float v = src[zoff + (size_t)(r0 + i) * Ccols + c0 + tx];
        if (gamma) v *= gamma[blockIdx.z * R + r0 + i];
        tile[i][tx] = v;
    }
    __syncthreads();
    int tid = ty * 32 + tx;
    int i = tid >> 3, jp = tid & 7;
    float v0 = tile[jp*4+0][i], v1 = tile[jp*4+1][i];
    float v2 = tile[jp*4+2][i], v3 = tile[jp*4+3][i];
    uint32_t h01 = __byte_perm(__float_as_uint(v0), __float_as_uint(v1), 0x7632);
    uint32_t h23 = __byte_perm(__float_as_uint(v2), __float_as_uint(v3), 0x7632);
    float l0 = v0 - __uint_as_float(__float_as_uint(v0) & 0xFFFF0000u);
    float l1 = v1 - __uint_as_float(__float_as_uint(v1) & 0xFFFF0000u);
    float l2 = v2 - __uint_as_float(__float_as_uint(v2) & 0xFFFF0000u);
    float l3 = v3 - __uint_as_float(__float_as_uint(v3) & 0xFFFF0000u);
    uint32_t l01, l23;
    asm("cvt.rn.bf16x2.f32 %0, %1, %2;" : "=r"(l01) : "f"(l1), "f"(l0));
    asm("cvt.rn.bf16x2.f32 %0, %1, %2;" : "=r"(l23) : "f"(l3), "f"(l2));
    int k0 = r0 + jp * 4;
    size_t o = dz + ((size_t)(c0 + i) * (R >> 5) + (k0 >> 5)) * 64 + (k0 & 31);
    *(uint2*)(dp + o)      = make_uint2(h01, h23);
    *(uint2*)(dp + o + 32) = make_uint2(l01, l23);
}

// ---------------- kv bias row: bias[l][n] = sum_k b[l][k] * w[l][k][n] ---
__global__ void kvbias_kernel(const float* __restrict__ lb,
                              const float* __restrict__ w) {
    int l = blockIdx.y;
    int n = blockIdx.x * 256 + threadIdx.x;
    const float* bb = lb + l * DIMD;
    const float* ww = w + (size_t)l * DIMD * KV2;
    float s = 0.f;
    #pragma unroll 8
    for (int k = 0; k < DIMD; k++) s += bb[k] * ww[(size_t)k * KV2 + n];
    g_kvbias[l * KV2 + n] = s;
}

// ---------------- broadcast latents --------------------------------------
__global__ void bcast_kernel(const float* __restrict__ lat) {
    int i = blockIdx.x * 256 + threadIdx.x;
    int row = i >> 10;
    int col = i & 1023;
    g_lat[i] = lat[((row & (NLAT-1)) << 10) + col];
}

// ---------------- LayerNorm core -----------------------------------------
__device__ __forceinline__ void ln_stats(const float* __restrict__ x, int t,
                                         float* red, float* v, float& mu, float& inv) {
    float s = 0.f;
    #pragma unroll
    for (int i = 0; i < 4; i++) { v[i] = x[t + 256*i]; s += v[i]; }
    red[t] = s; __syncthreads();
    #pragma unroll
    for (int o = 128; o > 0; o >>= 1) { if (t < o) red[t] += red[t+o]; __syncthreads(); }
    mu = red[0] * (1.f/DIMD);
    __syncthreads();
    float s2 = 0.f;
    #pragma unroll
    for (int i = 0; i < 4; i++) { float d = v[i]-mu; s2 += d*d; }
    red[t] = s2; __syncthreads();
    #pragma unroll
    for (int o = 128; o > 0; o >>= 1) { if (t < o) red[t] += red[t+o]; __syncthreads(); }
    inv = rsqrtf(red[0]*(1.f/DIMD) + 1e-5f);
}

// fp32 output (final LN)
__global__ void ln_kernel(const float* __restrict__ in,
                          const float* __restrict__ gg,
                          const float* __restrict__ bb,
                          float* __restrict__ out) {
    __shared__ float red[256];
    int row = blockIdx.x, t = threadIdx.x;
    float v[4], mu, inv;
    ln_stats(in + (size_t)row * DIMD, t, red, v, mu, inv);
    float* y = out + (size_t)row * DIMD;
    #pragma unroll
    for (int i = 0; i < 4; i++) { int c = t + 256*i; y[c] = (v[i]-mu)*inv*gg[c] + bb[c]; }
}

// packed split output (latent LNs)
__global__ void ln_split_kernel(const float* __restrict__ in,
                                const float* __restrict__ gg,
                                const float* __restrict__ bb,
                                uint16_t* __restrict__ op) {
    __shared__ float red[256];
    int row = blockIdx.x, t = threadIdx.x;
    float v[4], mu, inv;
    ln_stats(in + (size_t)row * DIMD, t, red, v, mu, inv);
    #pragma unroll
    for (int i = 0; i < 4; i++) {
        int c = t + 256*i;
        float y = (v[i]-mu)*inv*gg[c] + bb[c];
        size_t o = ((size_t)row * (DIMD >> 5) + (c >> 5)) * 64 + (c & 31);
        op[o]      = hi16(y);
        op[o + 32] = lo16(y);
    }
}

// media LN (gamma/beta folded into weights/bias), compaction gather, once
__global__ void ln_media_split_kernel(const float* __restrict__ x) {
    int r = blockIdx.x;
    int bt = r >> 10, i = r & (NMED-1);
    int b = bt >> 2;
    if (i >= g_cnt[b]) return;
    int src = (bt << 10) + g_cidx[b * NMED + i];
    __shared__ float red[256];
    int t = threadIdx.x;
    float v[4], mu, inv;
    ln_stats(x + (size_t)src * DIMD, t, red, v, mu, inv);
    #pragma unroll
    for (int j = 0; j < 4; j++) {
        int c = t + 256*j;
        float y = (v[j]-mu)*inv;
        size_t o = ((size_t)r * (DIMD >> 5) + (c >> 5)) * 64 + (c & 31);
        g_xm_p[o]      = hi16(y);
        g_xm_p[o + 32] = lo16(y);
    }
}

// ---- scores: block = (bt, h, jt) ----------------------------------------
__global__ void __launch_bounds__(256)
scores_kernel() {
    int bt = blockIdx.x, h = blockIdx.y, jt = blockIdx.z;
    int b  = bt >> 2;
    int j0 = jt * 128;
    int t = threadIdx.x;
    int cnt = g_cnt[b];
    size_t base = ((size_t)(bt*NH + h)) * NLAT;

    if (j0 < NMED && j0 >= cnt) {
        for (int idx = t; idx < 128*128; idx += 256) {
            int i = idx >> 7, j = idx & 127;
            g_s[(base + i)*NKV + j0 + j] = -INFINITY;
        }
        return;
    }

    __shared__ float Qs[32][129];
    __shared__ float Ks[32][129];
    int tx = t & 15, ty = t >> 4;

    float acc[8][8];
    #pragma unroll
    for (int i = 0; i < 8; i++)
        #pragma unroll
        for (int j = 0; j < 8; j++) acc[i][j] = 0.f;

    for (int dc = 0; dc < DHEAD; dc += 32) {
        for (int idx = t; idx < 128*32; idx += 256) {
            int i = idx >> 5, d = idx & 31;
            Qs[d][i] = g_q[((size_t)(bt*NLAT + i))*INNER + h*DHEAD + dc + d];
        }
        for (int idx = t; idx < 128*32; idx += 256) {
            int jj = idx >> 5, d = idx & 31;
            int j = j0 + jj;
            float kv = (j < NMED)
                ? g_kvx[((size_t)(bt*NMED + j))*KV2 + h*DHEAD + dc + d]
                : g_kvl[((size_t)(bt*NLAT + (j - NMED)))*KV2 + h*DHEAD + dc + d];
            Ks[d][jj] = kv;
        }
        __syncthreads();
        #pragma unroll 8
        for (int d = 0; d < 32; d++) {
            float ra[8], rb[8];
            #pragma unroll
            for (int i = 0; i < 8; i++) ra[i] = Qs[d][ty*8 + i];
            #pragma unroll
            for (int j = 0; j < 4; j++) { rb[j] = Ks[d][tx*4 + j]; rb[j+4] = Ks[d][64 + tx*4 + j]; }
            #pragma unroll
            for (int i = 0; i < 8; i++)
                #pragma unroll
                for (int j = 0; j < 8; j++) acc[i][j] += ra[i]*rb[j];
        }
        __syncthreads();
    }

    #pragma unroll
    for (int i = 0; i < 8; i++) {
        int row = ty*8 + i;
        #pragma unroll
        for (int j = 0; j < 8; j++) {
            int cc = (j < 4) ? (tx*4 + j) : (64 + tx*4 + j - 4);
            int jg = j0 + cc;
            float v = acc[i][j];
            if (jg < NMED && jg >= cnt) v = -INFINITY;
            g_s[(base + row)*NKV + jg] = v;
        }
    }
}

// ---------------- softmax over 1152 KV -----------------------------------
__global__ void softmax_kernel() {
    size_t row = blockIdx.x;
    float* s = g_s + row * (size_t)NKV;
    int t = threadIdx.x;
    __shared__ float red[256];
    float m = -INFINITY;
    for (int j = t; j < NKV; j += 256) m = fmaxf(m, s[j]);
    red[t] = m; __syncthreads();
    #pragma unroll
    for (int o = 128; o > 0; o >>= 1) { if (t < o) red[t] = fmaxf(red[t], red[t+o]); __syncthreads(); }
    m = red[0]; __syncthreads();
    float e[5]; int c = 0; float sum = 0.f;
    for (int j = t; j < NKV; j += 256) { e[c] = expf(s[j] - m); sum += e[c]; c++; }
    red[t] = sum; __syncthreads();
    #pragma unroll
    for (int o = 128; o > 0; o >>= 1) { if (t < o) red[t] += red[t+o]; __syncthreads(); }
    float inv = 1.f / red[0];
    c = 0;
    for (int j = t; j < NKV; j += 256) { s[j] = e[c] * inv; c++; }
}

// ---------------- O = P V (writes packed split) --------------------------
__global__ void __launch_bounds__(256)
av_kernel() {
    int bt = blockIdx.x, h = blockIdx.y;
    int b = bt >> 2;
    int cnt = g_cnt[b];
    __shared__ float Ps[32][133];
    __shared__ float Vs[32][96];
    int t = threadIdx.x, tx = t & 15, ty = t >> 4;

    float acc[8][6];
    #pragma unroll
    for (int i = 0; i < 8; i++)
        #pragma unroll
        for (int d = 0; d < 6; d++) acc[i][d] = 0.f;

    size_t prow0 = (size_t)(bt*NH + h) * NLAT;
    for (int jc = 0; jc < NKV; jc += 32) {
        if (jc < NMED && jc >= cnt) continue;
        for (int idx = t; idx < 128*32; idx += 256) {
            int i = idx >> 5, jj = idx & 31;
            Ps[jj][i] = g_s[(prow0 + i)*NKV + jc + jj];
        }
        for (int idx = t; idx < 32*96; idx += 256) {
            int jj = idx / 96, d = idx % 96;
            int j = jc + jj;
            float vv;
            if (j < NMED) {
                vv = (j < cnt) ? g_kvx[((size_t)(bt*NMED + j))*KV2 + INNER + h*DHEAD + d] : 0.f;
            } else {
                vv = g_kvl[((size_t)(bt*NLAT + (j - NMED)))*KV2 + INNER + h*DHEAD + d];
            }
            Vs[jj][d] = vv;
        }
        __syncthreads();
        #pragma unroll 8
        for (int jj = 0; jj < 32; jj++) {
            float ra[8], rb[6];
            #pragma unroll
            for (int i = 0; i < 8; i++) ra[i] = Ps[jj][ty*8 + i];
            #pragma unroll
            for (int d = 0; d < 6; d++) rb[d] = Vs[jj][tx + 16*d];
            #pragma unroll
            for (int i = 0; i < 8; i++)
                #pragma unroll
                for (int d = 0; d < 6; d++) acc[i][d] += ra[i]*rb[d];
        }
        __syncthreads();
    }

    #pragma unroll
    for (int i = 0; i < 8; i++)
        #pragma unroll
        for (int d = 0; d < 6; d++) {
            int row = bt*NLAT + ty*8 + i;
            int k = h*DHEAD + tx + 16*d;
            float v = acc[i][d];
            size_t o = ((size_t)row * (INNER >> 5) + (k >> 5)) * 64 + (k & 31);
            g_o_p[o]      = hi16(v);
            g_o_p[o + 32] = lo16(v);
        }
}

// ---------------- host orchestration (graph-capturable) ------------------
extern "C" void kernel_launch(void* const* d_in, const int* in_sizes, int n_in,
                              void* d_out, int out_size) {
    (void)in_sizes; (void)n_in; (void)out_size;
    const float* x       = (const float*)d_in[0];
    const float* vmask   = (const float*)d_in[1];
    const float* latents = (const float*)d_in[2];
    const float* ln_m_g  = (const float*)d_in[3];
    const float* ln_m_b  = (const float*)d_in[4];
    const float* ln_l_g  = (const float*)d_in[5];
    const float* ln_l_b  = (const float*)d_in[6];
    const float* q_w     = (const float*)d_in[7];
    const float* kv_w    = (const float*)d_in[8];
    const float* out_w   = (const float*)d_in[9];
    const float* ff_ln_g = (const float*)d_in[10];
    const float* ff_ln_b = (const float*)d_in[11];
    const float* ff_w1   = (const float*)d_in[12];
    const float* ff_w2   = (const float*)d_in[13];
    const float* fn_g    = (const float*)d_in[14];
    const float* fn_b    = (const float*)d_in[15];
    float* out = (float*)d_out;

    float *p_lat, *p_q, *p_kvl, *p_kvx, *p_bias;
    uint16_t *p_lm, *p_xm, *p_o, *p_h;
    uint16_t *p_qw, *p_kv, *p_kvm, *p_ow, *p_f1, *p_f2;
    cudaGetSymbolAddress((void**)&p_lat, g_lat);
    cudaGetSymbolAddress((void**)&p_q,   g_q);
    cudaGetSymbolAddress((void**)&p_kvl, g_kvl);
    cudaGetSymbolAddress((void**)&p_kvx, g_kvx);
    cudaGetSymbolAddress((void**)&p_bias, g_kvbias);
    cudaGetSymbolAddress((void**)&p_lm,  g_lm_p);
    cudaGetSymbolAddress((void**)&p_xm,  g_xm_p);
    cudaGetSymbolAddress((void**)&p_o,   g_o_p);
    cudaGetSymbolAddress((void**)&p_h,   g_h_p);
    cudaGetSymbolAddress((void**)&p_qw,  g_qwT_p);
    cudaGetSymbolAddress((void**)&p_kv,  g_kvT_p);
    cudaGetSymbolAddress((void**)&p_kvm, g_kvTm_p);
    cudaGetSymbolAddress((void**)&p_ow,  g_outT_p);
    cudaGetSymbolAddress((void**)&p_f1,  g_ff1T_p);
    cudaGetSymbolAddress((void**)&p_f2,  g_ff2T_p);

    cudaFuncSetAttribute((const void*)tgemm<0,0>, cudaFuncAttributeMaxDynamicSharedMemorySize, SMEM_TG);
    cudaFuncSetAttribute((const void*)tgemm<3,1>, cudaFuncAttributeMaxDynamicSharedMemorySize, SMEM_TG);
    cudaFuncSetAttribute((const void*)tgemm<1,0>, cudaFuncAttributeMaxDynamicSharedMemorySize, SMEM_TG);
    cudaFuncSetAttribute((const void*)tgemm<2,0>, cudaFuncAttributeMaxDynamicSharedMemorySize, SMEM_TG);

    const float scale = 1.0f / sqrtf((float)DHEAD);
    dim3 tb(32, 8);

    // one-time weight prep: transpose + packed bf16 split (media kv folds gamma)
    transpose_split_kernel<<<dim3(INNER/32, DIMD/32, NLAYER), tb>>>(q_w,   p_qw,  DIMD,  INNER, nullptr);
    transpose_split_kernel<<<dim3(KV2/32,   DIMD/32, NLAYER), tb>>>(kv_w,  p_kv,  DIMD,  KV2,   nullptr);
    transpose_split_kernel<<<dim3(KV2/32,   DIMD/32, NLAYER), tb>>>(kv_w,  p_kvm, DIMD,  KV2,   ln_m_g);
    transpose_split_kernel<<<dim3(DIMD/32, INNER/32, NLAYER), tb>>>(out_w, p_ow,  INNER, DIMD,  nullptr);
    transpose_split_kernel<<<dim3(DFF/32,   DIMD/32, NLAYER), tb>>>(ff_w1, p_f1,  DIMD,  DFF,   nullptr);
    transpose_split_kernel<<<dim3(DIMD/32,  DFF/32,  NLAYER), tb>>>(ff_w2, p_f2,  DFF,   DIMD,  nullptr);
    kvbias_kernel<<<dim3(KV2/256, NLAYER), 256>>>(ln_m_b, kv_w);

    compact_kernel<<<8, 1024>>>(vmask);
    bcast_kernel<<<RL*DIMD/256, 256>>>(latents);
    ln_media_split_kernel<<<XROWS, 256>>>(x);   // once: gamma/beta folded

    for (int l = 0; l < NLAYER; l++) {
        ln_split_kernel<<<RL, 256>>>(p_lat, ln_l_g + l*DIMD, ln_l_b + l*DIMD, p_lm);

        tgemm<0,0><<<dim3(INNER/128, RL/128), 256, SMEM_TG>>>(
            p_lm, p_qw + (size_t)l*INNER*2*DIMD, p_q, nullptr, nullptr,
            RL, INNER, DIMD, scale);
        tgemm<0,0><<<dim3(KV2/128, RL/128), 256, SMEM_TG>>>(
            p_lm, p_kv + (size_t)l*KV2*2*DIMD, p_kvl, nullptr, nullptr,
            RL, KV2, DIMD, 1.f);
        tgemm<3,1><<<dim3(KV2/128, XROWS/128), 256, SMEM_TG>>>(
            p_xm, p_kvm + (size_t)l*KV2*2*DIMD, p_kvx, nullptr, p_bias + l*KV2,
            XROWS, KV2, DIMD, 1.f);

        scores_kernel<<<dim3(BT, NH, NKV/128), 256>>>();
        softmax_kernel<<<BT*NH*NLAT, 256>>>();
        av_kernel<<<dim3(BT, NH), 256>>>();

        tgemm<1,0><<<dim3(DIMD/128, RL/128), 256, SMEM_TG>>>(
            p_o, p_ow + (size_t)l*DIMD*2*INNER, p_lat, nullptr, nullptr,
            RL, DIMD, INNER, 1.f);

        ln_split_kernel<<<RL, 256>>>(p_lat, ff_ln_g + l*DIMD, ff_ln_b + l*DIMD, p_lm);
        tgemm<2,0><<<dim3(DFF/128, RL/128), 256, SMEM_TG>>>(
            p_lm, p_f1 + (size_t)l*DFF*2*DIMD, nullptr, p_h, nullptr,
            RL, DFF, DIMD, 1.f);
        tgemm<1,0><<<dim3(DIMD/128, RL/128), 256, SMEM_TG>>>(
            p_h, p_f2 + (size_t)l*DIMD*2*DFF, p_lat, nullptr, nullptr,
            RL, DIMD, DFF, 1.f);
    }

    ln_kernel<<<RL, 256>>>(p_lat, fn_g, fn_b, out);
}

// round 15
// speedup vs baseline: 1.8163x; 1.6857x over previous
#include <cuda_runtime.h>
#include <math.h>
#include <stdint.h>

#define NLAYER 6
#define NH     16
#define DHEAD  96
#define DIMD   1024
#define INNER  1536
#define DFF    4096
#define NLAT   128
#define BT     32                 /* b*T sites                */
#define NMED   1024               /* media tokens per site    */
#define XROWS  (BT*NMED)          /* 32768 media rows total   */
#define RL     (BT*NLAT)          /* 4096 latent rows total   */
#define NKV    (NMED+NLAT)        /* 1152 KV per site         */
#define KV2    (2*INNER)          /* 3072 */

// ---------------- scratch (device globals; no allocation) ----------------
__device__ float g_lat[(size_t)RL*DIMD];
__device__ float g_lm [(size_t)RL*DIMD];
__device__ float g_xm [(size_t)XROWS*DIMD];     // xhat (no gamma/beta), once
__device__ float g_q  [(size_t)RL*INNER];
__device__ float g_kvl[(size_t)RL*KV2];
__device__ float g_kvx[(size_t)XROWS*KV2];
__device__ float g_o  [(size_t)RL*INNER];
__device__ float g_s  [(size_t)BT*NH*NLAT*NKV];
__device__ float g_h  [(size_t)RL*DFF];
__device__ int   g_cnt[8];
__device__ int   g_cidx[8*NMED];
__device__ float g_kvbias[NLAYER*KV2];
// transposed weights (B operands K-major: [N][K]) fp32
__device__ float g_qwT [(size_t)NLAYER*INNER*DIMD];
__device__ float g_kvT [(size_t)NLAYER*KV2*DIMD];
__device__ float g_kvTm[(size_t)NLAYER*KV2*DIMD];   // gamma-folded (media)
__device__ float g_outT[(size_t)NLAYER*DIMD*INNER];
__device__ float g_ff1T[(size_t)NLAYER*DFF*DIMD];
__device__ float g_ff2T[(size_t)NLAYER*DIMD*DFF];

// ======================= PTX helpers =====================================
__device__ __forceinline__ uint32_t smem_u32(const void* p) {
    uint32_t r;
    asm("{ .reg .u64 t; cvta.to.shared.u64 t, %1; cvt.u32.u64 %0, t; }"
        : "=r"(r) : "l"(p));
    return r;
}

__device__ __forceinline__ void ldsm4(uint32_t* r, uint32_t a) {
    asm volatile("ldmatrix.sync.aligned.m8n8.x4.shared.b16 {%0,%1,%2,%3}, [%4];"
        : "=r"(r[0]), "=r"(r[1]), "=r"(r[2]), "=r"(r[3]) : "r"(a));
}
__device__ __forceinline__ void ldsm2(uint32_t* r, uint32_t a) {
    asm volatile("ldmatrix.sync.aligned.m8n8.x2.shared.b16 {%0,%1}, [%2];"
        : "=r"(r[0]), "=r"(r[1]) : "r"(a));
}
__device__ __forceinline__ void mma16816(float* c, const uint32_t* a, const uint32_t* b) {
    asm volatile("mma.sync.aligned.m16n8k16.row.col.f32.bf16.bf16.f32 "
        "{%0,%1,%2,%3}, {%4,%5,%6,%7}, {%8,%9}, {%0,%1,%2,%3};"
        : "+f"(c[0]), "+f"(c[1]), "+f"(c[2]), "+f"(c[3])
        : "r"(a[0]), "r"(a[1]), "r"(a[2]), "r"(a[3]), "r"(b[0]), "r"(b[1]));
}

// ======================= bf16x3 tensor-core GEMM =========================
// C[M,N] = epi(alpha * A[M,K] @ Bt[N,K]^T).  M,N multiples of 128; K of 32.
// EPI: 0 = alpha* ; 1 = C += ; 2 = gelu_exact ; 3 = + bias[col]
// fp32 operands read from gmem; hi/lo bf16 split done in staging.
#define ROWB   80
#define T_AHI  0
#define T_ALO  10240
#define T_BHI  20480
#define T_BLO  30720
#define STGSZ  40960
#define SMEM_TG (2*STGSZ)

template<int EPI, int CNT_SKIP>
__global__ void __launch_bounds__(256, 2)
tgemm(const float* __restrict__ A, const float* __restrict__ Bt,
      float* __restrict__ C, const float* __restrict__ bias,
      int M, int N, int K, float alpha) {
    if (CNT_SKIP) {
        int by = blockIdx.y;
        int b  = by >> 5;
        if ((by & 7) * 128 >= g_cnt[b]) return;
    }
    extern __shared__ char smem[];
    const uint32_t sb = smem_u32(smem);
    const int t = threadIdx.x;
    const int lane = t & 31, wid = t >> 5;
    const int wm = (wid >> 2) * 64;
    const int wn = (wid & 3) * 32;
    const int m0 = blockIdx.y * 128, n0 = blockIdx.x * 128;

    const float* Ab = A  + (size_t)m0 * K;
    const float* Bb = Bt + (size_t)n0 * K;

    float acc[4][4][4];
    #pragma unroll
    for (int i = 0; i < 4; i++)
        #pragma unroll
        for (int j = 0; j < 4; j++)
            #pragma unroll
            for (int r = 0; r < 4; r++) acc[i][j][r] = 0.f;

    const int nch = K / 32;

    auto stage = [&](int c, int buf) {
        char* st = smem + buf * STGSZ;
        #pragma unroll
        for (int j = 0; j < 4; j++) {
            int idx = t + 256 * j;
            int row = idx >> 3, q = idx & 7;
            float4 v = *(const float4*)(Ab + (size_t)row * K + c * 32 + q * 4);
            uint32_t h01 = __byte_perm(__float_as_uint(v.x), __float_as_uint(v.y), 0x7632);
            uint32_t h23 = __byte_perm(__float_as_uint(v.z), __float_as_uint(v.w), 0x7632);
            float lx = v.x - __uint_as_float(__float_as_uint(v.x) & 0xFFFF0000u);
            float ly = v.y - __uint_as_float(__float_as_uint(v.y) & 0xFFFF0000u);
            float lz = v.z - __uint_as_float(__float_as_uint(v.z) & 0xFFFF0000u);
            float lw = v.w - __uint_as_float(__float_as_uint(v.w) & 0xFFFF0000u);
            uint32_t l01, l23;
            asm("cvt.rn.bf16x2.f32 %0, %1, %2;" : "=r"(l01) : "f"(ly), "f"(lx));
            asm("cvt.rn.bf16x2.f32 %0, %1, %2;" : "=r"(l23) : "f"(lw), "f"(lz));
            *(uint2*)(st + T_AHI + row * ROWB + q * 8) = make_uint2(h01, h23);
            *(uint2*)(st + T_ALO + row * ROWB + q * 8) = make_uint2(l01, l23);
            v = *(const float4*)(Bb + (size_t)row * K + c * 32 + q * 4);
            h01 = __byte_perm(__float_as_uint(v.x), __float_as_uint(v.y), 0x7632);
            h23 = __byte_perm(__float_as_uint(v.z), __float_as_uint(v.w), 0x7632);
            lx = v.x - __uint_as_float(__float_as_uint(v.x) & 0xFFFF0000u);
            ly = v.y - __uint_as_float(__float_as_uint(v.y) & 0xFFFF0000u);
            lz = v.z - __uint_as_float(__float_as_uint(v.z) & 0xFFFF0000u);
            lw = v.w - __uint_as_float(__float_as_uint(v.w) & 0xFFFF0000u);
            asm("cvt.rn.bf16x2.f32 %0, %1, %2;" : "=r"(l01) : "f"(ly), "f"(lx));
            asm("cvt.rn.bf16x2.f32 %0, %1, %2;" : "=r"(l23) : "f"(lw), "f"(lz));
            *(uint2*)(st + T_BHI + row * ROWB + q * 8) = make_uint2(h01, h23);
            *(uint2*)(st + T_BLO + row * ROWB + q * 8) = make_uint2(l01, l23);
        }
    };

    const int arow  = wm + (lane & 7) + ((lane >> 3) & 1) * 8;
    const int akoff = ((lane >> 4) & 1) * 16;
    const int brow  = wn + (lane & 7);
    const int bkoff = ((lane >> 3) & 1) * 16;

    stage(0, 0);
    __syncthreads();

    for (int c = 0; c < nch; c++) {
        if (c + 1 < nch) stage(c + 1, (c + 1) & 1);
        const uint32_t base = sb + (c & 1) * STGSZ;
        #pragma unroll
        for (int ks = 0; ks < 2; ks++) {
            uint32_t ah[4][4], al[4][4], bh[4][2], bl[4][2];
            #pragma unroll
            for (int mt = 0; mt < 4; mt++) {
                uint32_t ad = base + (uint32_t)(arow + mt * 16) * ROWB + ks * 32 + akoff;
                ldsm4(ah[mt], ad + T_AHI);
                ldsm4(al[mt], ad + T_ALO);
            }
            #pragma unroll
            for (int nt = 0; nt < 4; nt++) {
                uint32_t bd = base + (uint32_t)(brow + nt * 8) * ROWB + ks * 32 + bkoff;
                ldsm2(bh[nt], bd + T_BHI);
                ldsm2(bl[nt], bd + T_BLO);
            }
            #pragma unroll
            for (int mt = 0; mt < 4; mt++)
                #pragma unroll
                for (int nt = 0; nt < 4; nt++) {
                    mma16816(acc[mt][nt], ah[mt], bh[nt]);
                    mma16816(acc[mt][nt], ah[mt], bl[nt]);
                    mma16816(acc[mt][nt], al[mt], bh[nt]);
                }
        }
        __syncthreads();
    }

    const int rl = lane >> 2;
    const int cl = (lane & 3) * 2;
    #pragma unroll
    for (int mt = 0; mt < 4; mt++) {
        #pragma unroll
        for (int nt = 0; nt < 4; nt++) {
            int gr = m0 + wm + mt * 16 + rl;
            int gc = n0 + wn + nt * 8 + cl;
            float* p0 = C + (size_t)gr * N + gc;
            float* p1 = C + (size_t)(gr + 8) * N + gc;
            float2 v0 = make_float2(acc[mt][nt][0] * alpha, acc[mt][nt][1] * alpha);
            float2 v1 = make_float2(acc[mt][nt][2] * alpha, acc[mt][nt][3] * alpha);
            if (EPI == 3) {
                float b0 = bias[gc], b1 = bias[gc + 1];
                v0.x += b0; v0.y += b1; v1.x += b0; v1.y += b1;
            }
            if (EPI == 1) {
                float2 c0 = *(float2*)p0, c1 = *(float2*)p1;
                v0.x += c0.x; v0.y += c0.y; v1.x += c1.x; v1.y += c1.y;
            }
            if (EPI == 2) {
                v0.x = 0.5f * v0.x * (1.0f + erff(v0.x * 0.70710678118654752f));
                v0.y = 0.5f * v0.y * (1.0f + erff(v0.y * 0.70710678118654752f));
                v1.x = 0.5f * v1.x * (1.0f + erff(v1.x * 0.70710678118654752f));
                v1.y = 0.5f * v1.y * (1.0f + erff(v1.y * 0.70710678118654752f));
            }
            *(float2*)p0 = v0;
            *(float2*)p1 = v1;
        }
    }
}

// ---------------- mask compaction ----------------------------------------
__global__ void compact_kernel(const float* __restrict__ vmask) {
    int b = blockIdx.x, t = threadIdx.x;
    __shared__ int woff[32];
    int valid = (vmask[b * NMED + t] > 0.f) ? 1 : 0;
    unsigned bal = __ballot_sync(0xffffffffu, valid);
    int lane = t & 31, wid = t >> 5;
    int pre = __popc(bal & ((1u << lane) - 1u));
    if (lane == 31) woff[wid] = __popc(bal);
    __syncthreads();
    if (t == 0) {
        int s = 0;
        #pragma unroll
        for (int w = 0; w < 32; w++) { int c = woff[w]; woff[w] = s; s += c; }
        g_cnt[b] = s;
    }
    __syncthreads();
    if (valid) g_cidx[b * NMED + woff[wid] + pre] = t;
}

// ------ weight transpose: [R][C] -> [C][R], z = layer (+opt row gamma) ---
__global__ void transpose_kernel(const float* __restrict__ src,
                                 float* __restrict__ dst, int R, int Ccols,
                                 const float* __restrict__ gamma) {
    __shared__ float tile[32][33];
    size_t zoff = (size_t)blockIdx.z * R * Ccols;
    int r0 = blockIdx.y * 32, c0 = blockIdx.x * 32;
    int tx = threadIdx.x, ty = threadIdx.y;
    #pragma unroll
    for (int i = ty; i < 32; i += 8) {
        float v = src[zoff + (size_t)(r0 + i) * Ccols + c0 + tx];
        if (gamma) v *= gamma[blockIdx.z * R + r0 + i];
        tile[i][tx] = v;
    }
    __syncthreads();
    #pragma unroll
    for (int i = ty; i < 32; i += 8)
        dst[zoff + (size_t)(c0 + i) * R + r0 + tx] = tile[tx][i];
}

// ---------------- kv bias row: bias[l][n] = sum_k b[l][k] * w[l][k][n] ---
__global__ void kvbias_kernel(const float* __restrict__ lb,
                              const float* __restrict__ w) {
    int l = blockIdx.y;
    int n = blockIdx.x * 256 + threadIdx.x;
    const float* bb = lb + l * DIMD;
    const float* ww = w + (size_t)l * DIMD * KV2;
    float s = 0.f;
    #pragma unroll 8
    for (int k = 0; k < DIMD; k++) s += bb[k] * ww[(size_t)k * KV2 + n];
    g_kvbias[l * KV2 + n] = s;
}

// ---------------- broadcast latents --------------------------------------
__global__ void bcast_kernel(const float* __restrict__ lat) {
    int i = blockIdx.x * 256 + threadIdx.x;
    int row = i >> 10;
    int col = i & 1023;
    g_lat[i] = lat[((row & (NLAT-1)) << 10) + col];
}

// ---------------- LayerNorm ----------------------------------------------
__device__ __forceinline__ void ln_stats(const float* __restrict__ x, int t,
                                         float* red, float* v, float& mu, float& inv) {
    float s = 0.f;
    #pragma unroll
    for (int i = 0; i < 4; i++) { v[i] = x[t + 256*i]; s += v[i]; }
    red[t] = s; __syncthreads();
    #pragma unroll
    for (int o = 128; o > 0; o >>= 1) { if (t < o) red[t] += red[t+o]; __syncthreads(); }
    mu = red[0] * (1.f/DIMD);
    __syncthreads();
    float s2 = 0.f;
    #pragma unroll
    for (int i = 0; i < 4; i++) { float d = v[i]-mu; s2 += d*d; }
    red[t] = s2; __syncthreads();
    #pragma unroll
    for (int o = 128; o > 0; o >>= 1) { if (t < o) red[t] += red[t+o]; __syncthreads(); }
    inv = rsqrtf(red[0]*(1.f/DIMD) + 1e-5f);
}

__global__ void ln_kernel(const float* __restrict__ in,
                          const float* __restrict__ gg,
                          const float* __restrict__ bb,
                          float* __restrict__ out) {
    __shared__ float red[256];
    int row = blockIdx.x, t = threadIdx.x;
    float v[4], mu, inv;
    ln_stats(in + (size_t)row * DIMD, t, red, v, mu, inv);
    float* y = out + (size_t)row * DIMD;
    #pragma unroll
    for (int i = 0; i < 4; i++) { int c = t + 256*i; y[c] = (v[i]-mu)*inv*gg[c] + bb[c]; }
}

// media LN: xhat only (gamma folded into weights, beta into bias), once
__global__ void ln_media_kernel(const float* __restrict__ x) {
    int r = blockIdx.x;
    int bt = r >> 10, i = r & (NMED-1);
    int b = bt >> 2;
    if (i >= g_cnt[b]) return;
    int src = (bt << 10) + g_cidx[b * NMED + i];
    __shared__ float red[256];
    int t = threadIdx.x;
    float v[4], mu, inv;
    ln_stats(x + (size_t)src * DIMD, t, red, v, mu, inv);
    float* y = g_xm + (size_t)r * DIMD;
    #pragma unroll
    for (int j = 0; j < 4; j++) { int c = t + 256*j; y[c] = (v[j]-mu)*inv; }
}

// ---- scores: block = (bt, h, jt) ----------------------------------------
__global__ void __launch_bounds__(256)
scores_kernel() {
    int bt = blockIdx.x, h = blockIdx.y, jt = blockIdx.z;
    int b  = bt >> 2;
    int j0 = jt * 128;
    int t = threadIdx.x;
    int cnt = g_cnt[b];
    size_t base = ((size_t)(bt*NH + h)) * NLAT;

    if (j0 < NMED && j0 >= cnt) {
        for (int idx = t; idx < 128*128; idx += 256) {
            int i = idx >> 7, j = idx & 127;
            g_s[(base + i)*NKV + j0 + j] = -INFINITY;
        }
        return;
    }

    __shared__ float Qs[32][129];
    __shared__ float Ks[32][129];
    int tx = t & 15, ty = t >> 4;

    float acc[8][8];
    #pragma unroll
    for (int i = 0; i < 8; i++)
        #pragma unroll
        for (int j = 0; j < 8; j++) acc[i][j] = 0.f;

    for (int dc = 0; dc < DHEAD; dc += 32) {
        for (int idx = t; idx < 128*32; idx += 256) {
            int i = idx >> 5, d = idx & 31;
            Qs[d][i] = g_q[((size_t)(bt*NLAT + i))*INNER + h*DHEAD + dc + d];
        }
        for (int idx = t; idx < 128*32; idx += 256) {
            int jj = idx >> 5, d = idx & 31;
            int j = j0 + jj;
            float kv = (j < NMED)
                ? g_kvx[((size_t)(bt*NMED + j))*KV2 + h*DHEAD + dc + d]
                : g_kvl[((size_t)(bt*NLAT + (j - NMED)))*KV2 + h*DHEAD + dc + d];
            Ks[d][jj] = kv;
        }
        __syncthreads();
        #pragma unroll 8
        for (int d = 0; d < 32; d++) {
            float ra[8], rb[8];
            #pragma unroll
            for (int i = 0; i < 8; i++) ra[i] = Qs[d][ty*8 + i];
            #pragma unroll
            for (int j = 0; j < 4; j++) { rb[j] = Ks[d][tx*4 + j]; rb[j+4] = Ks[d][64 + tx*4 + j]; }
            #pragma unroll
            for (int i = 0; i < 8; i++)
                #pragma unroll
                for (int j = 0; j < 8; j++) acc[i][j] += ra[i]*rb[j];
        }
        __syncthreads();
    }

    #pragma unroll
    for (int i = 0; i < 8; i++) {
        int row = ty*8 + i;
        #pragma unroll
        for (int j = 0; j < 8; j++) {
            int cc = (j < 4) ? (tx*4 + j) : (64 + tx*4 + j - 4);
            int jg = j0 + cc;
            float v = acc[i][j];
            if (jg < NMED && jg >= cnt) v = -INFINITY;
            g_s[(base + row)*NKV + jg] = v;
        }
    }
}

// ---------------- softmax over 1152 KV -----------------------------------
__global__ void softmax_kernel() {
    size_t row = blockIdx.x;
    float* s = g_s + row * (size_t)NKV;
    int t = threadIdx.x;
    __shared__ float red[256];
    float m = -INFINITY;
    for (int j = t; j < NKV; j += 256) m = fmaxf(m, s[j]);
    red[t] = m; __syncthreads();
    #pragma unroll
    for (int o = 128; o > 0; o >>= 1) { if (t < o) red[t] = fmaxf(red[t], red[t+o]); __syncthreads(); }
    m = red[0]; __syncthreads();
    float e[5]; int c = 0; float sum = 0.f;
    for (int j = t; j < NKV; j += 256) { e[c] = expf(s[j] - m); sum += e[c]; c++; }
    red[t] = sum; __syncthreads();
    #pragma unroll
    for (int o = 128; o > 0; o >>= 1) { if (t < o) red[t] += red[t+o]; __syncthreads(); }
    float inv = 1.f / red[0];
    c = 0;
    for (int j = t; j < NKV; j += 256) { s[j] = e[c] * inv; c++; }
}

// ---------------- O = P V ------------------------------------------------
__global__ void __launch_bounds__(256)
av_kernel() {
    int bt = blockIdx.x, h = blockIdx.y;
    int b = bt >> 2;
    int cnt = g_cnt[b];
    __shared__ float Ps[32][133];
    __shared__ float Vs[32][96];
    int t = threadIdx.x, tx = t & 15, ty = t >> 4;

    float acc[8][6];
    #pragma unroll
    for (int i = 0; i < 8; i++)
        #pragma unroll
        for (int d = 0; d < 6; d++) acc[i][d] = 0.f;

    size_t prow0 = (size_t)(bt*NH + h) * NLAT;
    for (int jc = 0; jc < NKV; jc += 32) {
        if (jc < NMED && jc >= cnt) continue;
        for (int idx = t; idx < 128*32; idx += 256) {
            int i = idx >> 5, jj = idx & 31;
            Ps[jj][i] = g_s[(prow0 + i)*NKV + jc + jj];
        }
        for (int idx = t; idx < 32*96; idx += 256) {
            int jj = idx / 96, d = idx % 96;
            int j = jc + jj;
            float vv;
            if (j < NMED) {
                vv = (j < cnt) ? g_kvx[((size_t)(bt*NMED + j))*KV2 + INNER + h*DHEAD + d] : 0.f;
            } else {
                vv = g_kvl[((size_t)(bt*NLAT + (j - NMED)))*KV2 + INNER + h*DHEAD + d];
            }
            Vs[jj][d] = vv;
        }
        __syncthreads();
        #pragma unroll 8
        for (int jj = 0; jj < 32; jj++) {
            float ra[8], rb[6];
            #pragma unroll
            for (int i = 0; i < 8; i++) ra[i] = Ps[jj][ty*8 + i];
            #pragma unroll
            for (int d = 0; d < 6; d++) rb[d] = Vs[jj][tx + 16*d];
            #pragma unroll
            for (int i = 0; i < 8; i++)
                #pragma unroll
                for (int d = 0; d < 6; d++) acc[i][d] += ra[i]*rb[d];
        }
        __syncthreads();
    }

    #pragma unroll
    for (int i = 0; i < 8; i++)
        #pragma unroll
        for (int d = 0; d < 6; d++)
            g_o[((size_t)(bt*NLAT + ty*8 + i))*INNER + h*DHEAD + tx + 16*d] = acc[i][d];
}

// ---------------- host orchestration (graph-capturable) ------------------
extern "C" void kernel_launch(void* const* d_in, const int* in_sizes, int n_in,
                              void* d_out, int out_size) {
    (void)in_sizes; (void)n_in; (void)out_size;
    const float* x       = (const float*)d_in[0];
    const float* vmask   = (const float*)d_in[1];
    const float* latents = (const float*)d_in[2];
    const float* ln_m_g  = (const float*)d_in[3];
    const float* ln_m_b  = (const float*)d_in[4];
    const float* ln_l_g  = (const float*)d_in[5];
    const float* ln_l_b  = (const float*)d_in[6];
    const float* q_w     = (const float*)d_in[7];
    const float* kv_w    = (const float*)d_in[8];
    const float* out_w   = (const float*)d_in[9];
    const float* ff_ln_g = (const float*)d_in[10];
    const float* ff_ln_b = (const float*)d_in[11];
    const float* ff_w1   = (const float*)d_in[12];
    const float* ff_w2   = (const float*)d_in[13];
    const float* fn_g    = (const float*)d_in[14];
    const float* fn_b    = (const float*)d_in[15];
    float* out = (float*)d_out;

    float *p_lat, *p_lm, *p_xm, *p_q, *p_kvl, *p_kvx, *p_o, *p_h, *p_bias;
    float *p_qwT, *p_kvT, *p_kvTm, *p_outT, *p_ff1T, *p_ff2T;
    cudaGetSymbolAddress((void**)&p_lat, g_lat);
    cudaGetSymbolAddress((void**)&p_lm,  g_lm);
    cudaGetSymbolAddress((void**)&p_xm,  g_xm);
    cudaGetSymbolAddress((void**)&p_q,   g_q);
    cudaGetSymbolAddress((void**)&p_kvl, g_kvl);
    cudaGetSymbolAddress((void**)&p_kvx, g_kvx);
    cudaGetSymbolAddress((void**)&p_o,   g_o);
    cudaGetSymbolAddress((void**)&p_h,   g_h);
    cudaGetSymbolAddress((void**)&p_bias, g_kvbias);
    cudaGetSymbolAddress((void**)&p_qwT,  g_qwT);
    cudaGetSymbolAddress((void**)&p_kvT,  g_kvT);
    cudaGetSymbolAddress((void**)&p_kvTm, g_kvTm);
    cudaGetSymbolAddress((void**)&p_outT, g_outT);
    cudaGetSymbolAddress((void**)&p_ff1T, g_ff1T);
    cudaGetSymbolAddress((void**)&p_ff2T, g_ff2T);

    cudaFuncSetAttribute(tgemm<0,0>, cudaFuncAttributeMaxDynamicSharedMemorySize, SMEM_TG);
    cudaFuncSetAttribute(tgemm<3,1>, cudaFuncAttributeMaxDynamicSharedMemorySize, SMEM_TG);
    cudaFuncSetAttribute(tgemm<1,0>, cudaFuncAttributeMaxDynamicSharedMemorySize, SMEM_TG);
    cudaFuncSetAttribute(tgemm<2,0>, cudaFuncAttributeMaxDynamicSharedMemorySize, SMEM_TG);

    const float scale = 1.0f / sqrtf((float)DHEAD);
    dim3 tb(32, 8);

    // one-time weight prep (media kv folds LN gamma; beta -> bias row)
    transpose_kernel<<<dim3(INNER/32, DIMD/32, NLAYER), tb>>>(q_w,   p_qwT,  DIMD,  INNER, nullptr);
    transpose_kernel<<<dim3(KV2/32,   DIMD/32, NLAYER), tb>>>(kv_w,  p_kvT,  DIMD,  KV2,   nullptr);
    transpose_kernel<<<dim3(KV2/32,   DIMD/32, NLAYER), tb>>>(kv_w,  p_kvTm, DIMD,  KV2,   ln_m_g);
    transpose_kernel<<<dim3(DIMD/32, INNER/32, NLAYER), tb>>>(out_w, p_outT, INNER, DIMD,  nullptr);
    transpose_kernel<<<dim3(DFF/32,   DIMD/32, NLAYER), tb>>>(ff_w1, p_ff1T, DIMD,  DFF,   nullptr);
    transpose_kernel<<<dim3(DIMD/32,  DFF/32,  NLAYER), tb>>>(ff_w2, p_ff2T, DFF,   DIMD,  nullptr);
    kvbias_kernel<<<dim3(KV2/256, NLAYER), 256>>>(ln_m_b, kv_w);

    compact_kernel<<<8, 1024>>>(vmask);
    bcast_kernel<<<RL*DIMD/256, 256>>>(latents);
    ln_media_kernel<<<XROWS, 256>>>(x);       // once: xhat only

    for (int l = 0; l < NLAYER; l++) {
        ln_kernel<<<RL, 256>>>(p_lat, ln_l_g + l*DIMD, ln_l_b + l*DIMD, p_lm);

        tgemm<0,0><<<dim3(INNER/128, RL/128), 256, SMEM_TG>>>(
            p_lm, p_qwT + (size_t)l*INNER*DIMD, p_q, nullptr, RL, INNER, DIMD, scale);
        tgemm<0,0><<<dim3(KV2/128, RL/128), 256, SMEM_TG>>>(
            p_lm, p_kvT + (size_t)l*KV2*DIMD, p_kvl, nullptr, RL, KV2, DIMD, 1.f);
        tgemm<3,1><<<dim3(KV2/128, XROWS/128), 256, SMEM_TG>>>(
            p_xm, p_kvTm + (size_t)l*KV2*DIMD, p_kvx, p_bias + l*KV2, XROWS, KV2, DIMD, 1.f);

        scores_kernel<<<dim3(BT, NH, NKV/128), 256>>>();
        softmax_kernel<<<BT*NH*NLAT, 256>>>();
        av_kernel<<<dim3(BT, NH), 256>>>();

        tgemm<1,0><<<dim3(DIMD/128, RL/128), 256, SMEM_TG>>>(
            p_o, p_outT + (size_t)l*DIMD*INNER, p_lat, nullptr, RL, DIMD, INNER, 1.f);

        ln_kernel<<<RL, 256>>>(p_lat, ff_ln_g + l*DIMD, ff_ln_b + l*DIMD, p_lm);
        tgemm<2,0><<<dim3(DFF/128, RL/128), 256, SMEM_TG>>>(
            p_lm, p_ff1T + (size_t)l*DFF*DIMD, p_h, nullptr, RL, DFF, DIMD, 1.f);
        tgemm<1,0><<<dim3(DIMD/128, RL/128), 256, SMEM_TG>>>(
            p_h, p_ff2T + (size_t)l*DIMD*DFF, p_lat, nullptr, RL, DIMD, DFF, 1.f);
    }

    ln_kernel<<<RL, 256>>>(p_lat, fn_g, fn_b, out);
}

// round 17
// speedup vs baseline: 1.8799x; 1.0351x over previous
#include <cuda_runtime.h>
#include <math.h>
#include <stdint.h>

#define NLAYER 6
#define NH     16
#define DHEAD  96
#define DIMD   1024
#define INNER  1536
#define DFF    4096
#define NLAT   128
#define BT     32                 /* b*T sites                */
#define NMED   1024               /* media tokens per site    */
#define XROWS  (BT*NMED)          /* 32768 media rows total   */
#define RL     (BT*NLAT)          /* 4096 latent rows total   */
#define NKV    (NMED+NLAT)        /* 1152 KV per site         */
#define KV2    (2*INNER)          /* 3072 */

// ---------------- scratch (device globals; no allocation) ----------------
// packed split layout: per (row, kchunk) 128B = [32 x bf16 hi || 32 x bf16 lo]
// index(row,k) hi = (row*(K/32) + (k>>5))*64 + (k&31) ; lo = +32
__device__ float    g_lat[(size_t)RL*DIMD];
__device__ float    g_q  [(size_t)RL*INNER];
__device__ float    g_kvl[(size_t)RL*KV2];
__device__ float    g_kvx[(size_t)XROWS*KV2];
__device__ float    g_s  [(size_t)BT*NH*NLAT*NKV];
__device__ int      g_cnt[8];
__device__ int      g_cidx[8*NMED];
__device__ float    g_kvbias[NLAYER*KV2];
// packed activations
__device__ uint16_t g_lm_p[(size_t)RL*2*DIMD];
__device__ uint16_t g_xm_p[(size_t)XROWS*2*DIMD];
__device__ uint16_t g_o_p [(size_t)RL*2*INNER];
__device__ uint16_t g_h_p [(size_t)RL*2*DFF];
// packed transposed weights ([N][2K] K-major chunks)
__device__ uint16_t g_qwT_p [(size_t)NLAYER*INNER*2*DIMD];
__device__ uint16_t g_kvT_p [(size_t)NLAYER*KV2*2*DIMD];
__device__ uint16_t g_kvTm_p[(size_t)NLAYER*KV2*2*DIMD];
__device__ uint16_t g_outT_p[(size_t)NLAYER*DIMD*2*INNER];
__device__ uint16_t g_ff1T_p[(size_t)NLAYER*DFF*2*DIMD];
__device__ uint16_t g_ff2T_p[(size_t)NLAYER*DIMD*2*DFF];

// ======================= helpers =========================================
__device__ __forceinline__ uint32_t smem_u32(const void* p) {
    uint32_t r;
    asm("{ .reg .u64 t; cvta.to.shared.u64 t, %1; cvt.u32.u64 %0, t; }"
        : "=r"(r) : "l"(p));
    return r;
}
__device__ __forceinline__ uint16_t hi16(float v) {
    return (uint16_t)(__float_as_uint(v) >> 16);
}
__device__ __forceinline__ uint16_t lo16(float v) {
    float r = v - __uint_as_float(__float_as_uint(v) & 0xFFFF0000u);
    uint16_t o;
    asm("{.reg .b16 t; cvt.rn.bf16.f32 t, %1; mov.b16 %0, t;}" : "=h"(o) : "f"(r));
    return o;
}
__device__ __forceinline__ void ldsm4(uint32_t* r, uint32_t a) {
    asm volatile("ldmatrix.sync.aligned.m8n8.x4.shared.b16 {%0,%1,%2,%3}, [%4];"
        : "=r"(r[0]), "=r"(r[1]), "=r"(r[2]), "=r"(r[3]) : "r"(a));
}
__device__ __forceinline__ void ldsm2(uint32_t* r, uint32_t a) {
    asm volatile("ldmatrix.sync.aligned.m8n8.x2.shared.b16 {%0,%1}, [%2];"
        : "=r"(r[0]), "=r"(r[1]) : "r"(a));
}
__device__ __forceinline__ void mma16816(float* c, const uint32_t* a, const uint32_t* b) {
    asm volatile("mma.sync.aligned.m16n8k16.row.col.f32.bf16.bf16.f32 "
        "{%0,%1,%2,%3}, {%4,%5,%6,%7}, {%8,%9}, {%0,%1,%2,%3};"
        : "+f"(c[0]), "+f"(c[1]), "+f"(c[2]), "+f"(c[3])
        : "r"(a[0]), "r"(a[1]), "r"(a[2]), "r"(a[3]), "r"(b[0]), "r"(b[1]));
}

// ======================= bf16x3 tensor-core GEMM =========================
// C = epi(alpha * A @ Bt^T); A,B packed hi/lo chunk-interleaved in gmem.
// EPI: 0 = alpha* ; 1 = C += ; 2 = gelu -> packed Cp ; 3 = + bias[col]
#define ROWB   80
#define P_AHI  0
#define P_ALO  10304              /* +64B skew: hi/lo STS phases bank-disjoint */
#define P_BHI  20608
#define P_BLO  30912
#define STGSZ  41216
#define SMEM_TG (2*STGSZ)

template<int EPI, int CNT_SKIP>
__global__ void __launch_bounds__(256, 2)
tgemm(const uint16_t* __restrict__ Ap, const uint16_t* __restrict__ Bp,
      float* __restrict__ C, uint16_t* __restrict__ Cp,
      const float* __restrict__ bias, int M, int N, int K, float alpha) {
    if (CNT_SKIP) {
        int by = blockIdx.y;
        int b  = by >> 5;
        if ((by & 7) * 128 >= g_cnt[b]) return;
    }
    extern __shared__ char smem[];
    const uint32_t sb = smem_u32(smem);
    const int t = threadIdx.x;
    const int lane = t & 31, wid = t >> 5;
    const int wm = (wid >> 2) * 64;
    const int wn = (wid & 3) * 32;
    const int m0 = blockIdx.y * 128, n0 = blockIdx.x * 128;
    const int K2 = 2 * K;

    const uint16_t* Ar = Ap + (size_t)m0 * K2;
    const uint16_t* Br = Bp + (size_t)n0 * K2;

    float acc[4][4][4];
    #pragma unroll
    for (int i = 0; i < 4; i++)
        #pragma unroll
        for (int j = 0; j < 4; j++)
            #pragma unroll
            for (int r = 0; r < 4; r++) acc[i][j][r] = 0.f;

    const int nch = K / 32;
    const int qsel = t & 7;                      // thread-constant
    const uint32_t aplane = (qsel & 4) ? P_ALO : P_AHI;
    const uint32_t bplane = (qsel & 4) ? P_BLO : P_BHI;
    const uint32_t qoff   = (qsel & 3) * 16;

    auto stage = [&](int c, int buf) {
        char* st = smem + buf * STGSZ;
        #pragma unroll
        for (int h2 = 0; h2 < 4; h2++) {
            int r = (t >> 3) + 32 * h2;
            uint4 v = *(const uint4*)(Ar + (size_t)r * K2 + c * 64 + qsel * 8);
            *(uint4*)(st + aplane + r * ROWB + qoff) = v;
        }
        #pragma unroll
        for (int h2 = 0; h2 < 4; h2++) {
            int r = (t >> 3) + 32 * h2;
            uint4 v = *(const uint4*)(Br + (size_t)r * K2 + c * 64 + qsel * 8);
            *(uint4*)(st + bplane + r * ROWB + qoff) = v;
        }
    };

    const int arow  = wm + (lane & 7) + ((lane >> 3) & 1) * 8;
    const int akoff = ((lane >> 4) & 1) * 16;
    const int brow  = wn + (lane & 7);
    const int bkoff = ((lane >> 3) & 1) * 16;

    stage(0, 0);
    __syncthreads();

    for (int c = 0; c < nch; c++) {
        if (c + 1 < nch) stage(c + 1, (c + 1) & 1);
        const uint32_t base = sb + (c & 1) * STGSZ;
        #pragma unroll
        for (int ks = 0; ks < 2; ks++) {
            uint32_t ah[4][4], al[4][4], bh[4][2], bl[4][2];
            #pragma unroll
            for (int mt = 0; mt < 4; mt++) {
                uint32_t ad = base + (uint32_t)(arow + mt * 16) * ROWB + ks * 32 + akoff;
                ldsm4(ah[mt], ad + P_AHI);
                ldsm4(al[mt], ad + P_ALO);
            }
            #pragma unroll
            for (int nt = 0; nt < 4; nt++) {
                uint32_t bd = base + (uint32_t)(brow + nt * 8) * ROWB + ks * 32 + bkoff;
                ldsm2(bh[nt], bd + P_BHI);
                ldsm2(bl[nt], bd + P_BLO);
            }
            #pragma unroll
            for (int mt = 0; mt < 4; mt++)
                #pragma unroll
                for (int nt = 0; nt < 4; nt++) {
                    mma16816(acc[mt][nt], ah[mt], bh[nt]);
                    mma16816(acc[mt][nt], ah[mt], bl[nt]);
                    mma16816(acc[mt][nt], al[mt], bh[nt]);
                }
        }
        __syncthreads();
    }

    const int rl = lane >> 2;
    const int cl = (lane & 3) * 2;
    #pragma unroll
    for (int mt = 0; mt < 4; mt++) {
        #pragma unroll
        for (int nt = 0; nt < 4; nt++) {
            int gr = m0 + wm + mt * 16 + rl;
            int gc = n0 + wn + nt * 8 + cl;
            float2 v0 = make_float2(acc[mt][nt][0] * alpha, acc[mt][nt][1] * alpha);
            float2 v1 = make_float2(acc[mt][nt][2] * alpha, acc[mt][nt][3] * alpha);
            if (EPI == 3) {
                float b0 = bias[gc], b1 = bias[gc + 1];
                v0.x += b0; v0.y += b1; v1.x += b0; v1.y += b1;
            }
            if (EPI == 1) {
                size_t off0 = (size_t)gr * N + gc;
                size_t off1 = (size_t)(gr + 8) * N + gc;
                float2 c0 = *(float2*)(C + off0), c1 = *(float2*)(C + off1);
                v0.x += c0.x; v0.y += c0.y; v1.x += c1.x; v1.y += c1.y;
                *(float2*)(C + off0) = v0;
                *(float2*)(C + off1) = v1;
            } else if (EPI == 2) {
                v0.x = 0.5f * v0.x * (1.0f + erff(v0.x * 0.70710678118654752f));
                v0.y = 0.5f * v0.y * (1.0f + erff(v0.y * 0.70710678118654752f));
                v1.x = 0.5f * v1.x * (1.0f + erff(v1.x * 0.70710678118654752f));
                v1.y = 0.5f * v1.y * (1.0f + erff(v1.y * 0.70710678118654752f));
                uint32_t h0 = __byte_perm(__float_as_uint(v0.x), __float_as_uint(v0.y), 0x7632);
                uint32_t h1 = __byte_perm(__float_as_uint(v1.x), __float_as_uint(v1.y), 0x7632);
                float l0x = v0.x - __uint_as_float(__float_as_uint(v0.x) & 0xFFFF0000u);
                float l0y = v0.y - __uint_as_float(__float_as_uint(v0.y) & 0xFFFF0000u);
                float l1x = v1.x - __uint_as_float(__float_as_uint(v1.x) & 0xFFFF0000u);
                float l1y = v1.y - __uint_as_float(__float_as_uint(v1.y) & 0xFFFF0000u);
                uint32_t l0, l1;
                asm("cvt.rn.bf16x2.f32 %0, %1, %2;" : "=r"(l0) : "f"(l0y), "f"(l0x));
                asm("cvt.rn.bf16x2.f32 %0, %1, %2;" : "=r"(l1) : "f"(l1y), "f"(l1x));
                int chunk = gc >> 5, pos = gc & 31;
                size_t p0 = ((size_t)gr * (N >> 5) + chunk) * 64 + pos;
                size_t p1 = ((size_t)(gr + 8) * (N >> 5) + chunk) * 64 + pos;
                *(uint32_t*)(Cp + p0)      = h0;
                *(uint32_t*)(Cp + p0 + 32) = l0;
                *(uint32_t*)(Cp + p1)      = h1;
                *(uint32_t*)(Cp + p1 + 32) = l1;
            } else {
                size_t off0 = (size_t)gr * N + gc;
                size_t off1 = (size_t)(gr + 8) * N + gc;
                *(float2*)(C + off0) = v0;
                *(float2*)(C + off1) = v1;
            }
        }
    }
}

// ---------------- mask compaction ----------------------------------------
__global__ void compact_kernel(const float* __restrict__ vmask) {
    int b = blockIdx.x, t = threadIdx.x;
    __shared__ int woff[32];
    int valid = (vmask[b * NMED + t] > 0.f) ? 1 : 0;
    unsigned bal = __ballot_sync(0xffffffffu, valid);
    int lane = t & 31, wid = t >> 5;
    int pre = __popc(bal & ((1u << lane) - 1u));
    if (lane == 31) woff[wid] = __popc(bal);
    __syncthreads();
    if (t == 0) {
        int s = 0;
        #pragma unroll
        for (int w = 0; w < 32; w++) { int c = woff[w]; woff[w] = s; s += c; }
        g_cnt[b] = s;
    }
    __syncthreads();
    if (valid) g_cidx[b * NMED + woff[wid] + pre] = t;
}

// ------- weight transpose + split into packed layout (+opt row gamma) ----
__global__ void transpose_split_kernel(const float* __restrict__ src,
                                       uint16_t* __restrict__ dp,
                                       int R, int Ccols,
                                       const float* __restrict__ gamma) {
    __shared__ float tile[32][33];
    size_t zoff = (size_t)blockIdx.z * R * Ccols;
    size_t dz   = (size_t)blockIdx.z * Ccols * 2 * R;
    int r0 = blockIdx.y * 32, c0 = blockIdx.x * 32;
    int tx = threadIdx.x, ty = threadIdx.y;
    #pragma unroll
    for (int i = ty; i < 32; i += 8) {
        float v = src[zoff + (size_t)(r0 + i) * Ccols + c0 + tx];
        if (gamma) v *= gamma[blockIdx.z * R + r0 + i];
        tile[i][tx] = v;
    }
    __syncthreads();
    int tid = ty * 32 + tx;
    int i = tid >> 3, jp = tid & 7;
    float v0 = tile[jp*4+0][i], v1 = tile[jp*4+1][i];
    float v2 = tile[jp*4+2][i], v3 = tile[jp*4+3][i];
    uint32_t h01 = __byte_perm(__float_as_uint(v0), __float_as_uint(v1), 0x7632);
    uint32_t h23 = __byte_perm(__float_as_uint(v2), __float_as_uint(v3), 0x7632);
    float l0 = v0 - __uint_as_float(__float_as_uint(v0) & 0xFFFF0000u);
    float l1 = v1 - __uint_as_float(__float_as_uint(v1) & 0xFFFF0000u);
    float l2 = v2 - __uint_as_float(__float_as_uint(v2) & 0xFFFF0000u);
    float l3 = v3 - __uint_as_float(__float_as_uint(v3) & 0xFFFF0000u);
    uint32_t l01, l23;
    asm("cvt.rn.bf16x2.f32 %0, %1, %2;" : "=r"(l01) : "f"(l1), "f"(l0));
    asm("cvt.rn.bf16x2.f32 %0, %1, %2;" : "=r"(l23) : "f"(l3), "f"(l2));
    int k0 = r0 + jp * 4;
    size_t o = dz + ((size_t)(c0 + i) * (R >> 5) + (k0 >> 5)) * 64 + (k0 & 31);
    *(uint2*)(dp + o)      = make_uint2(h01, h23);
    *(uint2*)(dp + o + 32) = make_uint2(l01, l23);
}

// ---------------- kv bias row: bias[l][n] = sum_k b[l][k] * w[l][k][n] ---
__global__ void kvbias_kernel(const float* __restrict__ lb,
                              const float* __restrict__ w) {
    int l = blockIdx.y;
    int n = blockIdx.x * 256 + threadIdx.x;
    const float* bb = lb + l * DIMD;
    const float* ww = w + (size_t)l * DIMD * KV2;
    float s = 0.f;
    #pragma unroll 8
    for (int k = 0; k < DIMD; k++) s += bb[k] * ww[(size_t)k * KV2 + n];
    g_kvbias[l * KV2 + n] = s;
}

// ---------------- broadcast latents --------------------------------------
__global__ void bcast_kernel(const float* __restrict__ lat) {
    int i = blockIdx.x * 256 + threadIdx.x;
    int row = i >> 10;
    int col = i & 1023;
    g_lat[i] = lat[((row & (NLAT-1)) << 10) + col];
}

// ---------------- LayerNorm core -----------------------------------------
__device__ __forceinline__ void ln_stats(const float* __restrict__ x, int t,
                                         float* red, float* v, float& mu, float& inv) {
    float s = 0.f;
    #pragma unroll
    for (int i = 0; i < 4; i++) { v[i] = x[t + 256*i]; s += v[i]; }
    red[t] = s; __syncthreads();
    #pragma unroll
    for (int o = 128; o > 0; o >>= 1) { if (t < o) red[t] += red[t+o]; __syncthreads(); }
    mu = red[0] * (1.f/DIMD);
    __syncthreads();
    float s2 = 0.f;
    #pragma unroll
    for (int i = 0; i < 4; i++) { float d = v[i]-mu; s2 += d*d; }
    red[t] = s2; __syncthreads();
    #pragma unroll
    for (int o = 128; o > 0; o >>= 1) { if (t < o) red[t] += red[t+o]; __syncthreads(); }
    inv = rsqrtf(red[0]*(1.f/DIMD) + 1e-5f);
}

// fp32 output (final LN)
__global__ void ln_kernel(const float* __restrict__ in,
                          const float* __restrict__ gg,
                          const float* __restrict__ bb,
                          float* __restrict__ out) {
    __shared__ float red[256];
    int row = blockIdx.x, t = threadIdx.x;
    float v[4], mu, inv;
    ln_stats(in + (size_t)row * DIMD, t, red, v, mu, inv);
    float* y = out + (size_t)row * DIMD;
    #pragma unroll
    for (int i = 0; i < 4; i++) { int c = t + 256*i; y[c] = (v[i]-mu)*inv*gg[c] + bb[c]; }
}

// packed split output (latent LNs)
__global__ void ln_split_kernel(const float* __restrict__ in,
                                const float* __restrict__ gg,
                                const float* __restrict__ bb,
                                uint16_t* __restrict__ op) {
    __shared__ float red[256];
    int row = blockIdx.x, t = threadIdx.x;
    float v[4], mu, inv;
    ln_stats(in + (size_t)row * DIMD, t, red, v, mu, inv);
    #pragma unroll
    for (int i = 0; i < 4; i++) {
        int c = t + 256*i;
        float y = (v[i]-mu)*inv*gg[c] + bb[c];
        size_t o = ((size_t)row * (DIMD >> 5) + (c >> 5)) * 64 + (c & 31);
        op[o]      = hi16(y);
        op[o + 32] = lo16(y);
    }
}

// media LN (gamma/beta folded into weights/bias), compaction gather, once
__global__ void ln_media_split_kernel(const float* __restrict__ x) {
    int r = blockIdx.x;
    int bt = r >> 10, i = r & (NMED-1);
    int b = bt >> 2;
    if (i >= g_cnt[b]) return;
    int src = (bt << 10) + g_cidx[b * NMED + i];
    __shared__ float red[256];
    int t = threadIdx.x;
    float v[4], mu, inv;
    ln_stats(x + (size_t)src * DIMD, t, red, v, mu, inv);
    #pragma unroll
    for (int j = 0; j < 4; j++) {
        int c = t + 256*j;
        float y = (v[j]-mu)*inv;
        size_t o = ((size_t)r * (DIMD >> 5) + (c >> 5)) * 64 + (c & 31);
        g_xm_p[o]      = hi16(y);
        g_xm_p[o + 32] = lo16(y);
    }
}

// ---- scores: block = (bt, h, jt) ----------------------------------------
__global__ void __launch_bounds__(256)
scores_kernel() {
    int bt = blockIdx.x, h = blockIdx.y, jt = blockIdx.z;
    int b  = bt >> 2;
    int j0 = jt * 128;
    int t = threadIdx.x;
    int cnt = g_cnt[b];
    size_t base = ((size_t)(bt*NH + h)) * NLAT;

    if (j0 < NMED && j0 >= cnt) {
        for (int idx = t; idx < 128*128; idx += 256) {
            int i = idx >> 7, j = idx & 127;
            g_s[(base + i)*NKV + j0 + j] = -INFINITY;
        }
        return;
    }

    __shared__ float Qs[32][129];
    __shared__ float Ks[32][129];
    int tx = t & 15, ty = t >> 4;

    float acc[8][8];
    #pragma unroll
    for (int i = 0; i < 8; i++)
        #pragma unroll
        for (int j = 0; j < 8; j++) acc[i][j] = 0.f;

    for (int dc = 0; dc < DHEAD; dc += 32) {
        for (int idx = t; idx < 128*32; idx += 256) {
            int i = idx >> 5, d = idx & 31;
            Qs[d][i] = g_q[((size_t)(bt*NLAT + i))*INNER + h*DHEAD + dc + d];
        }
        for (int idx = t; idx < 128*32; idx += 256) {
            int jj = idx >> 5, d = idx & 31;
            int j = j0 + jj;
            float kv = (j < NMED)
                ? g_kvx[((size_t)(bt*NMED + j))*KV2 + h*DHEAD + dc + d]
                : g_kvl[((size_t)(bt*NLAT + (j - NMED)))*KV2 + h*DHEAD + dc + d];
            Ks[d][jj] = kv;
        }
        __syncthreads();
        #pragma unroll 8
        for (int d = 0; d < 32; d++) {
            float ra[8], rb[8];
            #pragma unroll
            for (int i = 0; i < 8; i++) ra[i] = Qs[d][ty*8 + i];
            #pragma unroll
            for (int j = 0; j < 4; j++) { rb[j] = Ks[d][tx*4 + j]; rb[j+4] = Ks[d][64 + tx*4 + j]; }
            #pragma unroll
            for (int i = 0; i < 8; i++)
                #pragma unroll
                for (int j = 0; j < 8; j++) acc[i][j] += ra[i]*rb[j];
        }
        __syncthreads();
    }

    #pragma unroll
    for (int i = 0; i < 8; i++) {
        int row = ty*8 + i;
        #pragma unroll
        for (int j = 0; j < 8; j++) {
            int cc = (j < 4) ? (tx*4 + j) : (64 + tx*4 + j - 4);
            int jg = j0 + cc;
            float v = acc[i][j];
            if (jg < NMED && jg >= cnt) v = -INFINITY;
            g_s[(base + row)*NKV + jg] = v;
        }
    }
}

// ---------------- softmax over 1152 KV -----------------------------------
__global__ void softmax_kernel() {
    size_t row = blockIdx.x;
    float* s = g_s + row * (size_t)NKV;
    int t = threadIdx.x;
    __shared__ float red[256];
    float m = -INFINITY;
    for (int j = t; j < NKV; j += 256) m = fmaxf(m, s[j]);
    red[t] = m; __syncthreads();
    #pragma unroll
    for (int o = 128; o > 0; o >>= 1) { if (t < o) red[t] = fmaxf(red[t], red[t+o]); __syncthreads(); }
    m = red[0]; __syncthreads();
    float e[5]; int c = 0; float sum = 0.f;
    for (int j = t; j < NKV; j += 256) { e[c] = expf(s[j] - m); sum += e[c]; c++; }
    red[t] = sum; __syncthreads();
    #pragma unroll
    for (int o = 128; o > 0; o >>= 1) { if (t < o) red[t] += red[t+o]; __syncthreads(); }
    float inv = 1.f / red[0];
    c = 0;
    for (int j = t; j < NKV; j += 256) { s[j] = e[c] * inv; c++; }
}

// ---------------- O = P V (writes packed split) --------------------------
__global__ void __launch_bounds__(256)
av_kernel() {
    int bt = blockIdx.x, h = blockIdx.y;
    int b = bt >> 2;
    int cnt = g_cnt[b];
    __shared__ float Ps[32][133];
    __shared__ float Vs[32][96];
    int t = threadIdx.x, tx = t & 15, ty = t >> 4;

    float acc[8][6];
    #pragma unroll
    for (int i = 0; i < 8; i++)
        #pragma unroll
        for (int d = 0; d < 6; d++) acc[i][d] = 0.f;

    size_t prow0 = (size_t)(bt*NH + h) * NLAT;
    for (int jc = 0; jc < NKV; jc += 32) {
        if (jc < NMED && jc >= cnt) continue;
        for (int idx = t; idx < 128*32; idx += 256) {
            int i = idx >> 5, jj = idx & 31;
            Ps[jj][i] = g_s[(prow0 + i)*NKV + jc + jj];
        }
        for (int idx = t; idx < 32*96; idx += 256) {
            int jj = idx / 96, d = idx % 96;
            int j = jc + jj;
            float vv;
            if (j < NMED) {
                vv = (j < cnt) ? g_kvx[((size_t)(bt*NMED + j))*KV2 + INNER + h*DHEAD + d] : 0.f;
            } else {
                vv = g_kvl[((size_t)(bt*NLAT + (j - NMED)))*KV2 + INNER + h*DHEAD + d];
            }
            Vs[jj][d] = vv;
        }
        __syncthreads();
        #pragma unroll 8
        for (int jj = 0; jj < 32; jj++) {
            float ra[8], rb[6];
            #pragma unroll
            for (int i = 0; i < 8; i++) ra[i] = Ps[jj][ty*8 + i];
            #pragma unroll
            for (int d = 0; d < 6; d++) rb[d] = Vs[jj][tx + 16*d];
            #pragma unroll
            for (int i = 0; i < 8; i++)
                #pragma unroll
                for (int d = 0; d < 6; d++) acc[i][d] += ra[i]*rb[d];
        }
        __syncthreads();
    }

    #pragma unroll
    for (int i = 0; i < 8; i++)
        #pragma unroll
        for (int d = 0; d < 6; d++) {
            int row = bt*NLAT + ty*8 + i;
            int k = h*DHEAD + tx + 16*d;
            float v = acc[i][d];
            size_t o = ((size_t)row * (INNER >> 5) + (k >> 5)) * 64 + (k & 31);
            g_o_p[o]      = hi16(v);
            g_o_p[o + 32] = lo16(v);
        }
}

// ---------------- host orchestration (graph-capturable) ------------------
extern "C" void kernel_launch(void* const* d_in, const int* in_sizes, int n_in,
                              void* d_out, int out_size) {
    (void)in_sizes; (void)n_in; (void)out_size;
    const float* x       = (const float*)d_in[0];
    const float* vmask   = (const float*)d_in[1];
    const float* latents = (const float*)d_in[2];
    const float* ln_m_g  = (const float*)d_in[3];
    const float* ln_m_b  = (const float*)d_in[4];
    const float* ln_l_g  = (const float*)d_in[5];
    const float* ln_l_b  = (const float*)d_in[6];
    const float* q_w     = (const float*)d_in[7];
    const float* kv_w    = (const float*)d_in[8];
    const float* out_w   = (const float*)d_in[9];
    const float* ff_ln_g = (const float*)d_in[10];
    const float* ff_ln_b = (const float*)d_in[11];
    const float* ff_w1   = (const float*)d_in[12];
    const float* ff_w2   = (const float*)d_in[13];
    const float* fn_g    = (const float*)d_in[14];
    const float* fn_b    = (const float*)d_in[15];
    float* out = (float*)d_out;

    float *p_lat, *p_q, *p_kvl, *p_kvx, *p_bias;
    uint16_t *p_lm, *p_xm, *p_o, *p_h;
    uint16_t *p_qw, *p_kv, *p_kvm, *p_ow, *p_f1, *p_f2;
    cudaGetSymbolAddress((void**)&p_lat, g_lat);
    cudaGetSymbolAddress((void**)&p_q,   g_q);
    cudaGetSymbolAddress((void**)&p_kvl, g_kvl);
    cudaGetSymbolAddress((void**)&p_kvx, g_kvx);
    cudaGetSymbolAddress((void**)&p_bias, g_kvbias);
    cudaGetSymbolAddress((void**)&p_lm,  g_lm_p);
    cudaGetSymbolAddress((void**)&p_xm,  g_xm_p);
    cudaGetSymbolAddress((void**)&p_o,   g_o_p);
    cudaGetSymbolAddress((void**)&p_h,   g_h_p);
    cudaGetSymbolAddress((void**)&p_qw,  g_qwT_p);
    cudaGetSymbolAddress((void**)&p_kv,  g_kvT_p);
    cudaGetSymbolAddress((void**)&p_kvm, g_kvTm_p);
    cudaGetSymbolAddress((void**)&p_ow,  g_outT_p);
    cudaGetSymbolAddress((void**)&p_f1,  g_ff1T_p);
    cudaGetSymbolAddress((void**)&p_f2,  g_ff2T_p);

    cudaFuncSetAttribute((const void*)tgemm<0,0>, cudaFuncAttributeMaxDynamicSharedMemorySize, SMEM_TG);
    cudaFuncSetAttribute((const void*)tgemm<3,1>, cudaFuncAttributeMaxDynamicSharedMemorySize, SMEM_TG);
    cudaFuncSetAttribute((const void*)tgemm<1,0>, cudaFuncAttributeMaxDynamicSharedMemorySize, SMEM_TG);
    cudaFuncSetAttribute((const void*)tgemm<2,0>, cudaFuncAttributeMaxDynamicSharedMemorySize, SMEM_TG);

    const float scale = 1.0f / sqrtf((float)DHEAD);
    dim3 tb(32, 8);

    // one-time weight prep: transpose + packed bf16 split (media kv folds gamma)
    transpose_split_kernel<<<dim3(INNER/32, DIMD/32, NLAYER), tb>>>(q_w,   p_qw,  DIMD,  INNER, nullptr);
    transpose_split_kernel<<<dim3(KV2/32,   DIMD/32, NLAYER), tb>>>(kv_w,  p_kv,  DIMD,  KV2,   nullptr);
    transpose_split_kernel<<<dim3(KV2/32,   DIMD/32, NLAYER), tb>>>(kv_w,  p_kvm, DIMD,  KV2,   ln_m_g);
    transpose_split_kernel<<<dim3(DIMD/32, INNER/32, NLAYER), tb>>>(out_w, p_ow,  INNER, DIMD,  nullptr);
    transpose_split_kernel<<<dim3(DFF/32,   DIMD/32, NLAYER), tb>>>(ff_w1, p_f1,  DIMD,  DFF,   nullptr);
    transpose_split_kernel<<<dim3(DIMD/32,  DFF/32,  NLAYER), tb>>>(ff_w2, p_f2,  DFF,   DIMD,  nullptr);
    kvbias_kernel<<<dim3(KV2/256, NLAYER), 256>>>(ln_m_b, kv_w);

    compact_kernel<<<8, 1024>>>(vmask);
    bcast_kernel<<<RL*DIMD/256, 256>>>(latents);
    ln_media_split_kernel<<<XROWS, 256>>>(x);   // once: gamma/beta folded

    for (int l = 0; l < NLAYER; l++) {
        ln_split_kernel<<<RL, 256>>>(p_lat, ln_l_g + l*DIMD, ln_l_b + l*DIMD, p_lm);

        tgemm<0,0><<<dim3(INNER/128, RL/128), 256, SMEM_TG>>>(
            p_lm, p_qw + (size_t)l*INNER*2*DIMD, p_q, nullptr, nullptr,
            RL, INNER, DIMD, scale);
        tgemm<0,0><<<dim3(KV2/128, RL/128), 256, SMEM_TG>>>(
            p_lm, p_kv + (size_t)l*KV2*2*DIMD, p_kvl, nullptr, nullptr,
            RL, KV2, DIMD, 1.f);
        tgemm<3,1><<<dim3(KV2/128, XROWS/128), 256, SMEM_TG>>>(
            p_xm, p_kvm + (size_t)l*KV2*2*DIMD, p_kvx, nullptr, p_bias + l*KV2,
            XROWS, KV2, DIMD, 1.f);

        scores_kernel<<<dim3(BT, NH, NKV/128), 256>>>();
        softmax_kernel<<<BT*NH*NLAT, 256>>>();
        av_kernel<<<dim3(BT, NH), 256>>>();

        tgemm<1,0><<<dim3(DIMD/128, RL/128), 256, SMEM_TG>>>(
            p_o, p_ow + (size_t)l*DIMD*2*INNER, p_lat, nullptr, nullptr,
            RL, DIMD, INNER, 1.f);

        ln_split_kernel<<<RL, 256>>>(p_lat, ff_ln_g + l*DIMD, ff_ln_b + l*DIMD, p_lm);
        tgemm<2,0><<<dim3(DFF/128, RL/128), 256, SMEM_TG>>>(
            p_lm, p_f1 + (size_t)l*DFF*2*DIMD, nullptr, p_h, nullptr,
            RL, DFF, DIMD, 1.f);
        tgemm<1,0><<<dim3(DIMD/128, RL/128), 256, SMEM_TG>>>(
            p_h, p_f2 + (size_t)l*DIMD*2*DFF, p_lat, nullptr, nullptr,
            RL, DIMD, DFF, 1.f);
    }

    ln_kernel<<<RL, 256>>>(p_lat, fn_g, fn_b, out);
}